// round 1
// baseline (speedup 1.0000x reference)
#include <cuda_runtime.h>
#include <mma.h>
#include <math.h>

using namespace nvcuda;

// ---------------- problem constants ----------------
constexpr int B_  = 128;
constexpr int T_  = 69;
constexpr int S_  = 77;    // 1 + NP + (T-1)
constexpr int D_  = 512;
constexpr int H_  = 8;
constexpr int DH_ = 64;
constexpr int NL_ = 12;
constexpr int FF_ = 2048;
constexpr int NP_ = 8;
constexpr int DG_ = 6;
constexpr int DS_ = 6;
constexpr int MROWS = B_ * S_;   // 9856

// ---------------- scratch (device globals; no runtime alloc) ----------------
__device__ float g_x [MROWS * D_];
__device__ float g_h [MROWS * D_];
__device__ float g_q [MROWS * D_];
__device__ float g_k [MROWS * D_];
__device__ float g_v [MROWS * D_];
__device__ float g_o [MROWS * D_];
__device__ float g_ff[MROWS * FF_];

// ---------------- embedding + prompt concat + pos emb ----------------
__global__ void embed_kernel(const int* __restrict__ tok,
                             const float* __restrict__ gp,
                             const float* __restrict__ temb,
                             const float* __restrict__ pemb,
                             float* __restrict__ x) {
    int idx = blockIdx.x * blockDim.x + threadIdx.x;   // < B_*S_*D_
    int d  = idx & (D_ - 1);
    int bs = idx >> 9;          // /512
    int s  = bs % S_;
    int b  = bs / S_;
    float v;
    if (s == 0) {
        v = temb[(size_t)tok[b * T_] * D_ + d];
    } else if (s <= NP_) {
        v = gp[((size_t)b * DG_) * NP_ * D_ + (s - 1) * D_ + d];
    } else {
        v = temb[(size_t)tok[b * T_ + (s - NP_)] * D_ + d];
    }
    x[idx] = v + pemb[s * D_ + d];
}

// replace positions 1..NP with fresh prompt (no pos emb)
__global__ void prompt_kernel(const float* __restrict__ p, int bstride,
                              float* __restrict__ x) {
    int idx = blockIdx.x * blockDim.x + threadIdx.x;   // < B_*NP_*D_
    int d  = idx & (D_ - 1);
    int r  = idx >> 9;
    int ps = r % NP_;
    int b  = r / NP_;
    x[((size_t)(b * S_ + 1 + ps)) * D_ + d] = p[(size_t)b * bstride + ps * D_ + d];
}

// ---------------- layernorm (one 128-thread block per row of 512) ----------------
__device__ __forceinline__ float2 block_sum2(float s, float ss) {
    __shared__ float sh1[4], sh2[4];
    int lane = threadIdx.x & 31, w = threadIdx.x >> 5;
    #pragma unroll
    for (int o = 16; o > 0; o >>= 1) {
        s  += __shfl_down_sync(0xffffffffu, s,  o);
        ss += __shfl_down_sync(0xffffffffu, ss, o);
    }
    if (lane == 0) { sh1[w] = s; sh2[w] = ss; }
    __syncthreads();
    float ts  = sh1[0] + sh1[1] + sh1[2] + sh1[3];
    float tss = sh2[0] + sh2[1] + sh2[2] + sh2[3];
    return make_float2(ts, tss);
}

__global__ void __launch_bounds__(128)
ln_kernel(const float* __restrict__ x, const float* __restrict__ g,
          const float* __restrict__ bb, float* __restrict__ out) {
    int row = blockIdx.x, tid = threadIdx.x;
    float4 vv = ((const float4*)(x + (size_t)row * D_))[tid];
    float s  = vv.x + vv.y + vv.z + vv.w;
    float ss = vv.x * vv.x + vv.y * vv.y + vv.z * vv.z + vv.w * vv.w;
    float2 tot = block_sum2(s, ss);
    float mean = tot.x * (1.0f / D_);
    float var  = tot.y * (1.0f / D_) - mean * mean;
    float rstd = rsqrtf(var + 1e-5f);
    float4 gv = ((const float4*)g)[tid];
    float4 bv = ((const float4*)bb)[tid];
    float4 ov;
    ov.x = (vv.x - mean) * rstd * gv.x + bv.x;
    ov.y = (vv.y - mean) * rstd * gv.y + bv.y;
    ov.z = (vv.z - mean) * rstd * gv.z + bv.z;
    ov.w = (vv.w - mean) * rstd * gv.w + bv.w;
    ((float4*)(out + (size_t)row * D_))[tid] = ov;
}

// ---------------- GEMM: C = epilogue(A @ W + bias), tf32x3 (fp32-accurate) ----------
// MODE 0: +bias    MODE 1: (+bias)*scale    MODE 2: +bias+res    MODE 3: gelu-ish
constexpr int BM = 64, BN = 64, BK = 32;

template<int MODE>
__global__ void __launch_bounds__(256)
gemm_tf32(const float* __restrict__ A, const float* __restrict__ Wt,
          const float* __restrict__ bias, const float* __restrict__ res,
          float* __restrict__ C, int M, int N, int K, float scale) {
    __shared__ float sA[BM][BK];
    __shared__ float sB[BK][BN];
    __shared__ float sC[BM][BN];

    int m0 = blockIdx.y * BM, n0 = blockIdx.x * BN;
    int tid = threadIdx.x;
    int wid = tid >> 5;
    int wm = wid & 3;          // 4 warps along M (16 rows each)
    int wn = wid >> 2;         // 2 warps along N (32 cols each)

    wmma::fragment<wmma::accumulator, 16, 16, 8, float> acc[2];
    wmma::fill_fragment(acc[0], 0.0f);
    wmma::fill_fragment(acc[1], 0.0f);

    for (int k0 = 0; k0 < K; k0 += BK) {
        // cooperative loads: A tile 64x32, B tile 32x64 (float4)
        int idx = tid;
        #pragma unroll
        for (int it = 0; it < 2; ++it, idx += 256) {
            int r = idx >> 3, c4 = idx & 7;
            *(float4*)&sA[r][c4 * 4] =
                *(const float4*)(A + (size_t)(m0 + r) * K + k0 + c4 * 4);
        }
        int idxB = tid;
        #pragma unroll
        for (int it = 0; it < 2; ++it, idxB += 256) {
            int r = idxB >> 4, c4 = idxB & 15;
            *(float4*)&sB[r][c4 * 4] =
                *(const float4*)(Wt + (size_t)(k0 + r) * N + n0 + c4 * 4);
        }
        __syncthreads();

        #pragma unroll
        for (int kk = 0; kk < BK; kk += 8) {
            wmma::fragment<wmma::matrix_a, 16, 16, 8, wmma::precision::tf32, wmma::row_major> ah, al;
            wmma::load_matrix_sync(ah, &sA[wm * 16][kk], BK);
            #pragma unroll
            for (int i = 0; i < ah.num_elements; i++) {
                float xv = ah.x[i];
                float hi = wmma::__float_to_tf32(xv);
                ah.x[i] = hi;
                al.x[i] = wmma::__float_to_tf32(xv - hi);
            }
            #pragma unroll
            for (int f = 0; f < 2; ++f) {
                wmma::fragment<wmma::matrix_b, 16, 16, 8, wmma::precision::tf32, wmma::row_major> bh, bl;
                wmma::load_matrix_sync(bh, &sB[kk][wn * 32 + f * 16], BN);
                #pragma unroll
                for (int i = 0; i < bh.num_elements; i++) {
                    float xv = bh.x[i];
                    float hi = wmma::__float_to_tf32(xv);
                    bh.x[i] = hi;
                    bl.x[i] = wmma::__float_to_tf32(xv - hi);
                }
                wmma::mma_sync(acc[f], ah, bh, acc[f]);   // hi*hi
                wmma::mma_sync(acc[f], ah, bl, acc[f]);   // hi*lo
                wmma::mma_sync(acc[f], al, bh, acc[f]);   // lo*hi
            }
        }
        __syncthreads();
    }

    wmma::store_matrix_sync(&sC[wm * 16][wn * 32],      acc[0], BN, wmma::mem_row_major);
    wmma::store_matrix_sync(&sC[wm * 16][wn * 32 + 16], acc[1], BN, wmma::mem_row_major);
    __syncthreads();

    #pragma unroll
    for (int it = 0; it < 16; ++it) {
        int idx = tid + it * 256;
        int r = idx >> 6, c = idx & 63;
        float vv = sC[r][c];
        int n = n0 + c;
        size_t off = (size_t)(m0 + r) * N + n;
        vv += bias[n];
        if (MODE == 1) vv *= scale;
        if (MODE == 2) vv += res[off];
        if (MODE == 3) vv = vv / (1.0f + __expf(-1.702f * vv));
        C[off] = vv;
    }
}

// ---------------- fused attention: one block per (b, h), fp32, causal+pad ------
__global__ void __launch_bounds__(128)
attn_kernel(const float* __restrict__ q, const float* __restrict__ k,
            const float* __restrict__ v, const int* __restrict__ amask,
            float* __restrict__ o) {
    __shared__ float sK[S_][DH_ + 1];   // pad to 65 -> conflict-free
    __shared__ float sV[S_][DH_ + 1];
    __shared__ float sQ[4][DH_];
    __shared__ float sP[4][S_ + 3];
    __shared__ int   sM[S_];
    int h = blockIdx.x, b = blockIdx.y;
    int tid = threadIdx.x, lane = tid & 31, w = tid >> 5;

    for (int i = tid; i < S_ * DH_; i += 128) {
        int s = i >> 6, d = i & 63;
        size_t off = ((size_t)(b * S_ + s)) * D_ + h * DH_ + d;
        sK[s][d] = k[off];
        sV[s][d] = v[off];
    }
    for (int i = tid; i < S_; i += 128)
        sM[i] = (i < NP_) ? 1 : amask[b * T_ + i - NP_];
    __syncthreads();

    for (int qi = w; qi < S_; qi += 4) {
        size_t qoff = ((size_t)(b * S_ + qi)) * D_ + h * DH_;
        sQ[w][lane]      = q[qoff + lane];
        sQ[w][lane + 32] = q[qoff + lane + 32];
        __syncwarp();
        int nj = qi + 1;          // causal: keys 0..qi
        float sc[3];
        #pragma unroll
        for (int t = 0; t < 3; t++) {
            int j = lane + 32 * t;
            float dsum = -3.0e38f;
            if (j < nj) {
                dsum = 0.0f;
                #pragma unroll
                for (int dd = 0; dd < DH_; dd++) dsum += sQ[w][dd] * sK[j][dd];
                if (sM[j] == 0) dsum = -1.0e30f;
            }
            sc[t] = dsum;
        }
        float m = fmaxf(sc[0], fmaxf(sc[1], sc[2]));
        #pragma unroll
        for (int o2 = 16; o2 > 0; o2 >>= 1) m = fmaxf(m, __shfl_xor_sync(0xffffffffu, m, o2));
        float e[3], esum = 0.0f;
        #pragma unroll
        for (int t = 0; t < 3; t++) {
            int j = lane + 32 * t;
            e[t] = (j < nj) ? __expf(sc[t] - m) : 0.0f;
            esum += e[t];
        }
        #pragma unroll
        for (int o2 = 16; o2 > 0; o2 >>= 1) esum += __shfl_xor_sync(0xffffffffu, esum, o2);
        float inv = 1.0f / esum;
        #pragma unroll
        for (int t = 0; t < 3; t++) {
            int j = lane + 32 * t;
            if (j < nj) sP[w][j] = e[t] * inv;
        }
        __syncwarp();
        float a0 = 0.0f, a1 = 0.0f;
        for (int j = 0; j < nj; j++) {
            float p = sP[w][j];
            a0 += p * sV[j][lane];
            a1 += p * sV[j][lane + 32];
        }
        o[qoff + lane]      = a0;
        o[qoff + lane + 32] = a1;
        __syncwarp();
    }
}

// ---------------- final: argmax(tokens)+NP gather + layernorm -> out ----------
__global__ void __launch_bounds__(128)
final_kernel(const float* __restrict__ x, const int* __restrict__ tok,
             const float* __restrict__ g, const float* __restrict__ bb,
             float* __restrict__ out) {
    int b = blockIdx.x, tid = threadIdx.x;
    __shared__ int sval[128];
    __shared__ int srow;
    sval[tid] = (tid < T_) ? tok[b * T_ + tid] : (-2147483647 - 1);
    __syncthreads();
    if (tid == 0) {
        int best = sval[0], bi = 0;
        for (int t = 1; t < T_; t++)
            if (sval[t] > best) { best = sval[t]; bi = t; }   // first max
        srow = bi + NP_;
    }
    __syncthreads();
    int row = b * S_ + srow;
    float4 vv = ((const float4*)(x + (size_t)row * D_))[tid];
    float s  = vv.x + vv.y + vv.z + vv.w;
    float ss = vv.x * vv.x + vv.y * vv.y + vv.z * vv.z + vv.w * vv.w;
    float2 tot = block_sum2(s, ss);
    float mean = tot.x * (1.0f / D_);
    float var  = tot.y * (1.0f / D_) - mean * mean;
    float rstd = rsqrtf(var + 1e-5f);
    float4 gv = ((const float4*)g)[tid];
    float4 bv = ((const float4*)bb)[tid];
    float4 ov;
    ov.x = (vv.x - mean) * rstd * gv.x + bv.x;
    ov.y = (vv.y - mean) * rstd * gv.y + bv.y;
    ov.z = (vv.z - mean) * rstd * gv.z + bv.z;
    ov.w = (vv.w - mean) * rstd * gv.w + bv.w;
    ((float4*)(out + (size_t)b * D_))[tid] = ov;
}

// ---------------- launch ----------------
extern "C" void kernel_launch(void* const* d_in, const int* in_sizes, int n_in,
                              void* d_out, int out_size) {
    (void)in_sizes; (void)n_in; (void)out_size;
    const int*   tok   = (const int*)  d_in[0];
    const int*   amask = (const int*)  d_in[1];
    const float* gp    = (const float*)d_in[2];
    const float* sp    = (const float*)d_in[3];
    const float* temb  = (const float*)d_in[4];
    const float* pemb  = (const float*)d_in[5];
    const float* ln1g  = (const float*)d_in[6];
    const float* ln1b  = (const float*)d_in[7];
    const float* Wq    = (const float*)d_in[8];
    const float* bq    = (const float*)d_in[9];
    const float* Wk    = (const float*)d_in[10];
    const float* bk    = (const float*)d_in[11];
    const float* Wv    = (const float*)d_in[12];
    const float* bv    = (const float*)d_in[13];
    const float* Wo    = (const float*)d_in[14];
    const float* bo    = (const float*)d_in[15];
    const float* ln2g  = (const float*)d_in[16];
    const float* ln2b  = (const float*)d_in[17];
    const float* W1    = (const float*)d_in[18];
    const float* b1    = (const float*)d_in[19];
    const float* W2    = (const float*)d_in[20];
    const float* b2    = (const float*)d_in[21];
    const float* lnfg  = (const float*)d_in[22];
    const float* lnfb  = (const float*)d_in[23];
    float* out = (float*)d_out;

    float *x, *hh, *qq, *kk, *vv, *oo, *ff;
    cudaGetSymbolAddress((void**)&x,  g_x);
    cudaGetSymbolAddress((void**)&hh, g_h);
    cudaGetSymbolAddress((void**)&qq, g_q);
    cudaGetSymbolAddress((void**)&kk, g_k);
    cudaGetSymbolAddress((void**)&vv, g_v);
    cudaGetSymbolAddress((void**)&oo, g_o);
    cudaGetSymbolAddress((void**)&ff, g_ff);

    embed_kernel<<<(B_ * S_ * D_) / 256, 256>>>(tok, gp, temb, pemb, x);

    dim3 gA(D_ / BN,  MROWS / BM);   // (8, 154)
    dim3 gF(FF_ / BN, MROWS / BM);   // (32, 154)

    for (int i = 0; i < NL_; i++) {
        if (i > 0) {
            const float* p; int bs;
            if (i < DG_) { p = gp + (size_t)i * NP_ * D_;            bs = DG_ * NP_ * D_; }
            else         { p = sp + (size_t)(i - (NL_ - DS_)) * NP_ * D_; bs = DS_ * NP_ * D_; }
            prompt_kernel<<<(B_ * NP_ * D_) / 256, 256>>>(p, bs, x);
        }
        ln_kernel<<<MROWS, 128>>>(x, ln1g + i * D_, ln1b + i * D_, hh);
        gemm_tf32<1><<<gA, 256>>>(hh, Wq + (size_t)i * D_ * D_, bq + i * D_, nullptr, qq, MROWS, D_, D_, 0.125f);
        gemm_tf32<0><<<gA, 256>>>(hh, Wk + (size_t)i * D_ * D_, bk + i * D_, nullptr, kk, MROWS, D_, D_, 1.0f);
        gemm_tf32<0><<<gA, 256>>>(hh, Wv + (size_t)i * D_ * D_, bv + i * D_, nullptr, vv, MROWS, D_, D_, 1.0f);
        attn_kernel<<<dim3(H_, B_), 128>>>(qq, kk, vv, amask, oo);
        gemm_tf32<2><<<gA, 256>>>(oo, Wo + (size_t)i * D_ * D_, bo + i * D_, x, x, MROWS, D_, D_, 1.0f);
        ln_kernel<<<MROWS, 128>>>(x, ln2g + i * D_, ln2b + i * D_, hh);
        gemm_tf32<3><<<gF, 256>>>(hh, W1 + (size_t)i * D_ * FF_, b1 + i * FF_, nullptr, ff, MROWS, FF_, D_, 1.0f);
        gemm_tf32<2><<<gA, 256>>>(ff, W2 + (size_t)i * FF_ * D_, b2 + i * D_, x, x, MROWS, D_, FF_, 1.0f);
    }
    final_kernel<<<B_, 128>>>(x, tok, lnfg, lnfb, out);
}

// round 2
// speedup vs baseline: 1.9432x; 1.9432x over previous
#include <cuda_runtime.h>
#include <cuda_bf16.h>
#include <mma.h>
#include <math.h>

using namespace nvcuda;
typedef __nv_bfloat16 bf16;

// ---------------- problem constants ----------------
constexpr int B_  = 128;
constexpr int T_  = 69;
constexpr int S_  = 77;
constexpr int D_  = 512;
constexpr int H_  = 8;
constexpr int DH_ = 64;
constexpr int NL_ = 12;
constexpr int FF_ = 2048;
constexpr int NP_ = 8;
constexpr int DG_ = 6;
constexpr int DS_ = 6;
constexpr int MROWS = B_ * S_;   // 9856
constexpr int QKVN  = 3 * D_;    // 1536

// ---------------- scratch (device globals; no runtime alloc) ----------------
__device__ float g_x  [MROWS * D_];
__device__ bf16  g_hhi[MROWS * D_];
__device__ bf16  g_hlo[MROWS * D_];
__device__ float g_qkv[MROWS * QKVN];
__device__ bf16  g_ohi[MROWS * D_];
__device__ bf16  g_olo[MROWS * D_];
__device__ bf16  g_fhi[MROWS * FF_];
__device__ bf16  g_flo[MROWS * FF_];

// weight splits (filled once per launch)
__device__ bf16  w_qkv_hi[NL_ * D_ * QKVN];
__device__ bf16  w_qkv_lo[NL_ * D_ * QKVN];
__device__ bf16  w_o_hi  [NL_ * D_ * D_];
__device__ bf16  w_o_lo  [NL_ * D_ * D_];
__device__ bf16  w_1_hi  [NL_ * D_ * FF_];
__device__ bf16  w_1_lo  [NL_ * D_ * FF_];
__device__ bf16  w_2_hi  [NL_ * FF_ * D_];
__device__ bf16  w_2_lo  [NL_ * FF_ * D_];
__device__ float g_bqkv  [NL_ * QKVN];

// ---------------- helpers ----------------
__device__ __forceinline__ void split1(float v, bf16* hi, bf16* lo, size_t off) {
    bf16 h = __float2bfloat16(v);
    hi[off] = h;
    lo[off] = __float2bfloat16(v - __bfloat162float(h));
}

// ---------------- weight split kernels ----------------
__global__ void split_kernel(const float* __restrict__ src,
                             bf16* __restrict__ hi, bf16* __restrict__ lo, int n) {
    int i = blockIdx.x * 256 + threadIdx.x;
    if (i >= n) return;
    float v = src[i];
    bf16 h = __float2bfloat16(v);
    hi[i] = h;
    lo[i] = __float2bfloat16(v - __bfloat162float(h));
}

__global__ void pack_qkv_kernel(const float* __restrict__ Wq, const float* __restrict__ Wk,
                                const float* __restrict__ Wv,
                                bf16* __restrict__ hi, bf16* __restrict__ lo) {
    int idx = blockIdx.x * 256 + threadIdx.x;       // < NL*D*QKVN
    int i   = idx / (D_ * QKVN);
    int rem = idx % (D_ * QKVN);
    int k = rem / QKVN, n = rem % QKVN;
    size_t wb = (size_t)i * D_ * D_ + (size_t)k * D_;
    float v;
    if (n < D_)          v = Wq[wb + n];
    else if (n < 2 * D_) v = Wk[wb + n - D_];
    else                 v = Wv[wb + n - 2 * D_];
    bf16 h = __float2bfloat16(v);
    hi[idx] = h;
    lo[idx] = __float2bfloat16(v - __bfloat162float(h));
}

__global__ void pack_bias_kernel(const float* __restrict__ bq, const float* __restrict__ bk,
                                 const float* __restrict__ bv, float* __restrict__ bqkv) {
    int idx = blockIdx.x * 256 + threadIdx.x;       // < NL*QKVN
    if (idx >= NL_ * QKVN) return;
    int i = idx / QKVN, n = idx % QKVN;
    float v;
    if (n < D_)          v = bq[i * D_ + n];
    else if (n < 2 * D_) v = bk[i * D_ + n - D_];
    else                 v = bv[i * D_ + n - 2 * D_];
    bqkv[idx] = v;
}

// ---------------- embedding + prompt concat + pos emb ----------------
__global__ void embed_kernel(const int* __restrict__ tok,
                             const float* __restrict__ gp,
                             const float* __restrict__ temb,
                             const float* __restrict__ pemb,
                             float* __restrict__ x) {
    int idx = blockIdx.x * blockDim.x + threadIdx.x;
    int d  = idx & (D_ - 1);
    int bs = idx >> 9;
    int s  = bs % S_;
    int b  = bs / S_;
    float v;
    if (s == 0) {
        v = temb[(size_t)tok[b * T_] * D_ + d];
    } else if (s <= NP_) {
        v = gp[((size_t)b * DG_) * NP_ * D_ + (s - 1) * D_ + d];
    } else {
        v = temb[(size_t)tok[b * T_ + (s - NP_)] * D_ + d];
    }
    x[idx] = v + pemb[s * D_ + d];
}

__global__ void prompt_kernel(const float* __restrict__ p, int bstride,
                              float* __restrict__ x) {
    int idx = blockIdx.x * blockDim.x + threadIdx.x;
    int d  = idx & (D_ - 1);
    int r  = idx >> 9;
    int ps = r % NP_;
    int b  = r / NP_;
    x[((size_t)(b * S_ + 1 + ps)) * D_ + d] = p[(size_t)b * bstride + ps * D_ + d];
}

// ---------------- layernorm -> bf16 hi/lo split ----------------
__device__ __forceinline__ float2 block_sum2(float s, float ss) {
    __shared__ float sh1[4], sh2[4];
    int lane = threadIdx.x & 31, w = threadIdx.x >> 5;
    #pragma unroll
    for (int o = 16; o > 0; o >>= 1) {
        s  += __shfl_down_sync(0xffffffffu, s,  o);
        ss += __shfl_down_sync(0xffffffffu, ss, o);
    }
    if (lane == 0) { sh1[w] = s; sh2[w] = ss; }
    __syncthreads();
    return make_float2(sh1[0] + sh1[1] + sh1[2] + sh1[3],
                       sh2[0] + sh2[1] + sh2[2] + sh2[3]);
}

__global__ void __launch_bounds__(128)
ln_split_kernel(const float* __restrict__ x, const float* __restrict__ g,
                const float* __restrict__ bb,
                bf16* __restrict__ hi, bf16* __restrict__ lo) {
    int row = blockIdx.x, tid = threadIdx.x;
    float4 vv = ((const float4*)(x + (size_t)row * D_))[tid];
    float s  = vv.x + vv.y + vv.z + vv.w;
    float ss = vv.x * vv.x + vv.y * vv.y + vv.z * vv.z + vv.w * vv.w;
    float2 tot = block_sum2(s, ss);
    float mean = tot.x * (1.0f / D_);
    float var  = tot.y * (1.0f / D_) - mean * mean;
    float rstd = rsqrtf(var + 1e-5f);
    float4 gv = ((const float4*)g)[tid];
    float4 bv = ((const float4*)bb)[tid];
    float4 ov;
    ov.x = (vv.x - mean) * rstd * gv.x + bv.x;
    ov.y = (vv.y - mean) * rstd * gv.y + bv.y;
    ov.z = (vv.z - mean) * rstd * gv.z + bv.z;
    ov.w = (vv.w - mean) * rstd * gv.w + bv.w;
    size_t o = (size_t)row * D_ + tid * 4;
    __nv_bfloat162 h01 = __floats2bfloat162_rn(ov.x, ov.y);
    __nv_bfloat162 h23 = __floats2bfloat162_rn(ov.z, ov.w);
    *(__nv_bfloat162*)(hi + o)     = h01;
    *(__nv_bfloat162*)(hi + o + 2) = h23;
    float lx = ov.x - __low2float(h01);
    float ly = ov.y - __high2float(h01);
    float lz = ov.z - __low2float(h23);
    float lw = ov.w - __high2float(h23);
    *(__nv_bfloat162*)(lo + o)     = __floats2bfloat162_rn(lx, ly);
    *(__nv_bfloat162*)(lo + o + 2) = __floats2bfloat162_rn(lz, lw);
}

// ---------------- GEMM: C = epi(Ahi/lo @ Bhi/lo + bias), bf16x3 (near-fp32) ----
// MODE 0: QKV (bias, scale q cols, fp32 out)
// MODE 1: bias + residual, fp32 out
// MODE 2: bias + gelu, bf16 hi/lo out
constexpr int BM = 128, BN = 64, BK = 32;

template<int MODE>
__global__ void __launch_bounds__(256, 2)
gemm_bf(const bf16* __restrict__ Ahi, const bf16* __restrict__ Alo,
        const bf16* __restrict__ Bhi, const bf16* __restrict__ Blo,
        const float* __restrict__ bias, const float* __restrict__ res,
        float* __restrict__ Cf, bf16* __restrict__ Chi, bf16* __restrict__ Clo,
        int M, int N, int K) {
    __shared__ __align__(16) unsigned char smem[BM * BN * 4];   // 32KB, reused
    bf16* sAhi = (bf16*)smem;            // BM*BK
    bf16* sAlo = sAhi + BM * BK;
    bf16* sBhi = sAlo + BM * BK;         // BK*BN
    bf16* sBlo = sBhi + BK * BN;
    float* sC  = (float*)smem;

    int m0 = blockIdx.y * BM, n0 = blockIdx.x * BN;
    int tid = threadIdx.x, wid = tid >> 5;
    int wm = wid & 3, wn = wid >> 2;

    wmma::fragment<wmma::accumulator, 16, 16, 16, float> acc[2][2];
    #pragma unroll
    for (int i = 0; i < 2; i++)
        #pragma unroll
        for (int j = 0; j < 2; j++)
            wmma::fill_fragment(acc[i][j], 0.0f);

    for (int k0 = 0; k0 < K; k0 += BK) {
        // A tile: 128x32 bf16 (hi+lo), 512 uint4 each
        #pragma unroll
        for (int t = 0; t < 2; t++) {
            int idx = tid + t * 256;
            int row = idx >> 2, c = (idx & 3) * 8;
            size_t g = (size_t)(m0 + row) * K + k0 + c;
            *(uint4*)(sAhi + row * BK + c) = *(const uint4*)(Ahi + g);
            *(uint4*)(sAlo + row * BK + c) = *(const uint4*)(Alo + g);
        }
        // B tile: 32x64 bf16 (hi+lo), 256 uint4 each
        {
            int row = tid >> 3, c = (tid & 7) * 8;
            size_t g = (size_t)(k0 + row) * N + n0 + c;
            *(uint4*)(sBhi + row * BN + c) = *(const uint4*)(Bhi + g);
            *(uint4*)(sBlo + row * BN + c) = *(const uint4*)(Blo + g);
        }
        __syncthreads();

        #pragma unroll
        for (int kk = 0; kk < BK; kk += 16) {
            wmma::fragment<wmma::matrix_a, 16, 16, 16, bf16, wmma::row_major> ah[2], al[2];
            wmma::fragment<wmma::matrix_b, 16, 16, 16, bf16, wmma::row_major> bh[2], bl[2];
            #pragma unroll
            for (int i = 0; i < 2; i++) {
                wmma::load_matrix_sync(ah[i], sAhi + (wm * 32 + i * 16) * BK + kk, BK);
                wmma::load_matrix_sync(al[i], sAlo + (wm * 32 + i * 16) * BK + kk, BK);
            }
            #pragma unroll
            for (int j = 0; j < 2; j++) {
                wmma::load_matrix_sync(bh[j], sBhi + kk * BN + wn * 32 + j * 16, BN);
                wmma::load_matrix_sync(bl[j], sBlo + kk * BN + wn * 32 + j * 16, BN);
            }
            #pragma unroll
            for (int i = 0; i < 2; i++)
                #pragma unroll
                for (int j = 0; j < 2; j++) {
                    wmma::mma_sync(acc[i][j], ah[i], bh[j], acc[i][j]);
                    wmma::mma_sync(acc[i][j], ah[i], bl[j], acc[i][j]);
                    wmma::mma_sync(acc[i][j], al[i], bh[j], acc[i][j]);
                }
        }
        __syncthreads();
    }

    #pragma unroll
    for (int i = 0; i < 2; i++)
        #pragma unroll
        for (int j = 0; j < 2; j++)
            wmma::store_matrix_sync(sC + (wm * 32 + i * 16) * BN + wn * 32 + j * 16,
                                    acc[i][j], BN, wmma::mem_row_major);
    __syncthreads();

    #pragma unroll
    for (int t = 0; t < 8; t++) {
        int idx = tid + t * 256;          // float4 units over 128x64
        int r = idx >> 4, c = (idx & 15) * 4;
        int n = n0 + c;
        size_t off = (size_t)(m0 + r) * N + n;
        float4 v = *(float4*)(sC + r * BN + c);
        float4 b4 = *(const float4*)(bias + n);
        v.x += b4.x; v.y += b4.y; v.z += b4.z; v.w += b4.w;
        if (MODE == 0) {
            float sc = (n < D_) ? 0.125f : 1.0f;
            v.x *= sc; v.y *= sc; v.z *= sc; v.w *= sc;
            *(float4*)(Cf + off) = v;
        } else if (MODE == 1) {
            float4 rr = *(const float4*)(res + off);
            v.x += rr.x; v.y += rr.y; v.z += rr.z; v.w += rr.w;
            *(float4*)(Cf + off) = v;
        } else {
            v.x = v.x / (1.0f + __expf(-1.702f * v.x));
            v.y = v.y / (1.0f + __expf(-1.702f * v.y));
            v.z = v.z / (1.0f + __expf(-1.702f * v.z));
            v.w = v.w / (1.0f + __expf(-1.702f * v.w));
            __nv_bfloat162 h01 = __floats2bfloat162_rn(v.x, v.y);
            __nv_bfloat162 h23 = __floats2bfloat162_rn(v.z, v.w);
            *(__nv_bfloat162*)(Chi + off)     = h01;
            *(__nv_bfloat162*)(Chi + off + 2) = h23;
            float lx = v.x - __low2float(h01);
            float ly = v.y - __high2float(h01);
            float lz = v.z - __low2float(h23);
            float lw = v.w - __high2float(h23);
            *(__nv_bfloat162*)(Clo + off)     = __floats2bfloat162_rn(lx, ly);
            *(__nv_bfloat162*)(Clo + off + 2) = __floats2bfloat162_rn(lz, lw);
        }
    }
}

// ---------------- fused attention: one block per (b, h), 256 threads ----------
__global__ void __launch_bounds__(256)
attn_kernel(const float* __restrict__ qkv, const int* __restrict__ amask,
            bf16* __restrict__ ohi, bf16* __restrict__ olo) {
    __shared__ float sK[S_][DH_ + 1];
    __shared__ float sV[S_][DH_ + 1];
    __shared__ float sQ[8][DH_];
    __shared__ float sP[8][S_ + 3];
    __shared__ int   sM[S_];
    int h = blockIdx.x, b = blockIdx.y;
    int tid = threadIdx.x, lane = tid & 31, w = tid >> 5;

    for (int i = tid; i < S_ * DH_; i += 256) {
        int s = i >> 6, d = i & 63;
        size_t base = ((size_t)(b * S_ + s)) * QKVN + h * DH_ + d;
        sK[s][d] = qkv[base + D_];
        sV[s][d] = qkv[base + 2 * D_];
    }
    for (int i = tid; i < S_; i += 256)
        sM[i] = (i < NP_) ? 1 : amask[b * T_ + i - NP_];
    __syncthreads();

    for (int qi = w; qi < S_; qi += 8) {
        size_t qoff = ((size_t)(b * S_ + qi)) * QKVN + h * DH_;
        sQ[w][lane]      = qkv[qoff + lane];
        sQ[w][lane + 32] = qkv[qoff + lane + 32];
        __syncwarp();
        int nj = qi + 1;
        float sc[3];
        #pragma unroll
        for (int t = 0; t < 3; t++) {
            int j = lane + 32 * t;
            float dsum = -3.0e38f;
            if (j < nj) {
                dsum = 0.0f;
                #pragma unroll
                for (int dd = 0; dd < DH_; dd++) dsum += sQ[w][dd] * sK[j][dd];
                if (sM[j] == 0) dsum = -1.0e30f;
            }
            sc[t] = dsum;
        }
        float m = fmaxf(sc[0], fmaxf(sc[1], sc[2]));
        #pragma unroll
        for (int o2 = 16; o2 > 0; o2 >>= 1) m = fmaxf(m, __shfl_xor_sync(0xffffffffu, m, o2));
        float e[3], esum = 0.0f;
        #pragma unroll
        for (int t = 0; t < 3; t++) {
            int j = lane + 32 * t;
            e[t] = (j < nj) ? __expf(sc[t] - m) : 0.0f;
            esum += e[t];
        }
        #pragma unroll
        for (int o2 = 16; o2 > 0; o2 >>= 1) esum += __shfl_xor_sync(0xffffffffu, esum, o2);
        float inv = 1.0f / esum;
        #pragma unroll
        for (int t = 0; t < 3; t++) {
            int j = lane + 32 * t;
            if (j < nj) sP[w][j] = e[t] * inv;
        }
        __syncwarp();
        float a0 = 0.0f, a1 = 0.0f;
        for (int j = 0; j < nj; j++) {
            float p = sP[w][j];
            a0 += p * sV[j][lane];
            a1 += p * sV[j][lane + 32];
        }
        size_t ooff = ((size_t)(b * S_ + qi)) * D_ + h * DH_;
        split1(a0, ohi, olo, ooff + lane);
        split1(a1, ohi, olo, ooff + lane + 32);
        __syncwarp();
    }
}

// ---------------- final: argmax(tokens)+NP gather + layernorm -> out ----------
__global__ void __launch_bounds__(128)
final_kernel(const float* __restrict__ x, const int* __restrict__ tok,
             const float* __restrict__ g, const float* __restrict__ bb,
             float* __restrict__ out) {
    int b = blockIdx.x, tid = threadIdx.x;
    __shared__ int sval[128];
    __shared__ int srow;
    sval[tid] = (tid < T_) ? tok[b * T_ + tid] : (-2147483647 - 1);
    __syncthreads();
    if (tid == 0) {
        int best = sval[0], bi = 0;
        for (int t = 1; t < T_; t++)
            if (sval[t] > best) { best = sval[t]; bi = t; }
        srow = bi + NP_;
    }
    __syncthreads();
    int row = b * S_ + srow;
    float4 vv = ((const float4*)(x + (size_t)row * D_))[tid];
    float s  = vv.x + vv.y + vv.z + vv.w;
    float ss = vv.x * vv.x + vv.y * vv.y + vv.z * vv.z + vv.w * vv.w;
    float2 tot = block_sum2(s, ss);
    float mean = tot.x * (1.0f / D_);
    float var  = tot.y * (1.0f / D_) - mean * mean;
    float rstd = rsqrtf(var + 1e-5f);
    float4 gv = ((const float4*)g)[tid];
    float4 bv = ((const float4*)bb)[tid];
    float4 ov;
    ov.x = (vv.x - mean) * rstd * gv.x + bv.x;
    ov.y = (vv.y - mean) * rstd * gv.y + bv.y;
    ov.z = (vv.z - mean) * rstd * gv.z + bv.z;
    ov.w = (vv.w - mean) * rstd * gv.w + bv.w;
    ((float4*)(out + (size_t)b * D_))[tid] = ov;
}

// ---------------- launch ----------------
extern "C" void kernel_launch(void* const* d_in, const int* in_sizes, int n_in,
                              void* d_out, int out_size) {
    (void)in_sizes; (void)n_in; (void)out_size;
    const int*   tok   = (const int*)  d_in[0];
    const int*   amask = (const int*)  d_in[1];
    const float* gp    = (const float*)d_in[2];
    const float* sp    = (const float*)d_in[3];
    const float* temb  = (const float*)d_in[4];
    const float* pemb  = (const float*)d_in[5];
    const float* ln1g  = (const float*)d_in[6];
    const float* ln1b  = (const float*)d_in[7];
    const float* Wq    = (const float*)d_in[8];
    const float* bq    = (const float*)d_in[9];
    const float* Wk    = (const float*)d_in[10];
    const float* bk    = (const float*)d_in[11];
    const float* Wv    = (const float*)d_in[12];
    const float* bv    = (const float*)d_in[13];
    const float* Wo    = (const float*)d_in[14];
    const float* bo    = (const float*)d_in[15];
    const float* ln2g  = (const float*)d_in[16];
    const float* ln2b  = (const float*)d_in[17];
    const float* W1    = (const float*)d_in[18];
    const float* b1    = (const float*)d_in[19];
    const float* W2    = (const float*)d_in[20];
    const float* b2    = (const float*)d_in[21];
    const float* lnfg  = (const float*)d_in[22];
    const float* lnfb  = (const float*)d_in[23];
    float* out = (float*)d_out;

    float *x, *qkv, *bqkv;
    bf16 *hhi, *hlo, *ohi, *olo, *fhi, *flo;
    bf16 *wqh, *wql, *woh, *wol, *w1h, *w1l, *w2h, *w2l;
    cudaGetSymbolAddress((void**)&x,   g_x);
    cudaGetSymbolAddress((void**)&hhi, g_hhi);
    cudaGetSymbolAddress((void**)&hlo, g_hlo);
    cudaGetSymbolAddress((void**)&qkv, g_qkv);
    cudaGetSymbolAddress((void**)&ohi, g_ohi);
    cudaGetSymbolAddress((void**)&olo, g_olo);
    cudaGetSymbolAddress((void**)&fhi, g_fhi);
    cudaGetSymbolAddress((void**)&flo, g_flo);
    cudaGetSymbolAddress((void**)&wqh, w_qkv_hi);
    cudaGetSymbolAddress((void**)&wql, w_qkv_lo);
    cudaGetSymbolAddress((void**)&woh, w_o_hi);
    cudaGetSymbolAddress((void**)&wol, w_o_lo);
    cudaGetSymbolAddress((void**)&w1h, w_1_hi);
    cudaGetSymbolAddress((void**)&w1l, w_1_lo);
    cudaGetSymbolAddress((void**)&w2h, w_2_hi);
    cudaGetSymbolAddress((void**)&w2l, w_2_lo);
    cudaGetSymbolAddress((void**)&bqkv, g_bqkv);

    // one-time (per launch) weight splitting / packing
    pack_qkv_kernel<<<(NL_ * D_ * QKVN) / 256, 256>>>(Wq, Wk, Wv, wqh, wql);
    pack_bias_kernel<<<(NL_ * QKVN + 255) / 256, 256>>>(bq, bk, bv, bqkv);
    split_kernel<<<(NL_ * D_ * D_) / 256, 256>>>(Wo, woh, wol, NL_ * D_ * D_);
    split_kernel<<<(NL_ * D_ * FF_) / 256, 256>>>(W1, w1h, w1l, NL_ * D_ * FF_);
    split_kernel<<<(NL_ * FF_ * D_) / 256, 256>>>(W2, w2h, w2l, NL_ * FF_ * D_);

    embed_kernel<<<(B_ * S_ * D_) / 256, 256>>>(tok, gp, temb, pemb, x);

    dim3 gQKV(QKVN / BN, MROWS / BM);  // (24, 77)
    dim3 gD  (D_   / BN, MROWS / BM);  // (8, 77)
    dim3 gFF (FF_  / BN, MROWS / BM);  // (32, 77)

    for (int i = 0; i < NL_; i++) {
        if (i > 0) {
            const float* p; int bs;
            if (i < DG_) { p = gp + (size_t)i * NP_ * D_;                 bs = DG_ * NP_ * D_; }
            else         { p = sp + (size_t)(i - (NL_ - DS_)) * NP_ * D_; bs = DS_ * NP_ * D_; }
            prompt_kernel<<<(B_ * NP_ * D_) / 256, 256>>>(p, bs, x);
        }
        ln_split_kernel<<<MROWS, 128>>>(x, ln1g + i * D_, ln1b + i * D_, hhi, hlo);
        gemm_bf<0><<<gQKV, 256>>>(hhi, hlo, wqh + (size_t)i * D_ * QKVN, wql + (size_t)i * D_ * QKVN,
                                  bqkv + i * QKVN, nullptr, qkv, nullptr, nullptr,
                                  MROWS, QKVN, D_);
        attn_kernel<<<dim3(H_, B_), 256>>>(qkv, amask, ohi, olo);
        gemm_bf<1><<<gD, 256>>>(ohi, olo, woh + (size_t)i * D_ * D_, wol + (size_t)i * D_ * D_,
                                bo + i * D_, x, x, nullptr, nullptr,
                                MROWS, D_, D_);
        ln_split_kernel<<<MROWS, 128>>>(x, ln2g + i * D_, ln2b + i * D_, hhi, hlo);
        gemm_bf<2><<<gFF, 256>>>(hhi, hlo, w1h + (size_t)i * D_ * FF_, w1l + (size_t)i * D_ * FF_,
                                 b1 + i * FF_, nullptr, nullptr, fhi, flo,
                                 MROWS, FF_, D_);
        gemm_bf<1><<<gD, 256>>>(fhi, flo, w2h + (size_t)i * FF_ * D_, w2l + (size_t)i * FF_ * D_,
                                b2 + i * D_, x, x, nullptr, nullptr,
                                MROWS, D_, FF_);
    }
    final_kernel<<<B_, 128>>>(x, tok, lnfg, lnfb, out);
}

// round 4
// speedup vs baseline: 5.7366x; 2.9521x over previous
#include <cuda_runtime.h>
#include <cuda_bf16.h>
#include <math.h>
#include <stdint.h>

typedef __nv_bfloat16 bf16;

// ---------------- problem constants ----------------
constexpr int B_  = 128;
constexpr int T_  = 69;
constexpr int S_  = 77;
constexpr int D_  = 512;
constexpr int H_  = 8;
constexpr int DH_ = 64;
constexpr int NL_ = 12;
constexpr int FF_ = 2048;
constexpr int NP_ = 8;
constexpr int DG_ = 6;
constexpr int DS_ = 6;
constexpr int MROWS = B_ * S_;   // 9856 = 77 * 128
constexpr int QKVN  = 3 * D_;    // 1536

// ---------------- scratch (device globals; no runtime alloc) ----------------
__device__ __align__(128) float g_x  [MROWS * D_];
__device__ __align__(128) bf16  g_hhi[MROWS * D_];
__device__ __align__(128) bf16  g_hlo[MROWS * D_];
__device__ __align__(128) float g_qkv[MROWS * QKVN];
__device__ __align__(128) bf16  g_ohi[MROWS * D_];
__device__ __align__(128) bf16  g_olo[MROWS * D_];
__device__ __align__(128) bf16  g_fhi[MROWS * FF_];
__device__ __align__(128) bf16  g_flo[MROWS * FF_];

// transposed weight splits [layer][N][K] (K-major)
__device__ __align__(128) bf16  w_qkv_hi[NL_ * QKVN * D_];
__device__ __align__(128) bf16  w_qkv_lo[NL_ * QKVN * D_];
__device__ __align__(128) bf16  w_o_hi  [NL_ * D_ * D_];
__device__ __align__(128) bf16  w_o_lo  [NL_ * D_ * D_];
__device__ __align__(128) bf16  w_1_hi  [NL_ * FF_ * D_];
__device__ __align__(128) bf16  w_1_lo  [NL_ * FF_ * D_];
__device__ __align__(128) bf16  w_2_hi  [NL_ * D_ * FF_];
__device__ __align__(128) bf16  w_2_lo  [NL_ * D_ * FF_];
__device__ float g_bqkv  [NL_ * QKVN];

// ---------------- PTX helpers (sm_80-feature set, plain-target legal) --------
__device__ __forceinline__ uint32_t smem_u32(const void* p) {
    uint32_t a;
    asm("{ .reg .u64 t; cvta.to.shared.u64 t, %1; cvt.u32.u64 %0, t; }" : "=r"(a) : "l"(p));
    return a;
}

#define CP16(saddr, gptr) \
    asm volatile("cp.async.cg.shared.global [%0], [%1], 16;" :: "r"(saddr), "l"(gptr) : "memory")
#define CP_COMMIT() asm volatile("cp.async.commit_group;" ::: "memory")
#define CP_WAIT1()  asm volatile("cp.async.wait_group 1;" ::: "memory")
#define CP_WAIT0()  asm volatile("cp.async.wait_group 0;" ::: "memory")

__device__ __forceinline__ void ldsm4(uint32_t* r, uint32_t addr) {
    asm volatile("ldmatrix.sync.aligned.m8n8.x4.shared.b16 {%0,%1,%2,%3}, [%4];"
                 : "=r"(r[0]), "=r"(r[1]), "=r"(r[2]), "=r"(r[3]) : "r"(addr));
}

__device__ __forceinline__ void mma16816(float* d, const uint32_t* a, const uint32_t* b) {
    asm volatile(
        "mma.sync.aligned.m16n8k16.row.col.f32.bf16.bf16.f32 "
        "{%0,%1,%2,%3}, {%4,%5,%6,%7}, {%8,%9}, {%0,%1,%2,%3};"
        : "+f"(d[0]), "+f"(d[1]), "+f"(d[2]), "+f"(d[3])
        : "r"(a[0]), "r"(a[1]), "r"(a[2]), "r"(a[3]), "r"(b[0]), "r"(b[1]));
}

// ---------------- weight transpose+split: out[n][k] = in[k][n] ----------------
__global__ void __launch_bounds__(256)
tsplit_kernel(const float* __restrict__ src, bf16* __restrict__ hi, bf16* __restrict__ lo,
              int K, int N, size_t srcStride, size_t dstStride) {
    __shared__ float t[32][33];
    int layer = blockIdx.z;
    src += (size_t)layer * srcStride;
    hi  += (size_t)layer * dstStride;
    lo  += (size_t)layer * dstStride;
    int n0 = blockIdx.x * 32, k0 = blockIdx.y * 32;
    int lx = threadIdx.x & 31, ly = threadIdx.x >> 5;
    #pragma unroll
    for (int i = ly; i < 32; i += 8)
        t[i][lx] = src[(size_t)(k0 + i) * N + n0 + lx];
    __syncthreads();
    #pragma unroll
    for (int i = ly; i < 32; i += 8) {
        float v = t[lx][i];
        size_t o = (size_t)(n0 + i) * K + k0 + lx;
        bf16 h = __float2bfloat16(v);
        hi[o] = h;
        lo[o] = __float2bfloat16(v - __bfloat162float(h));
    }
}

__global__ void pack_bias_kernel(const float* __restrict__ bq, const float* __restrict__ bk,
                                 const float* __restrict__ bv, float* __restrict__ bqkv) {
    int idx = blockIdx.x * 256 + threadIdx.x;
    if (idx >= NL_ * QKVN) return;
    int i = idx / QKVN, n = idx % QKVN;
    float v;
    if (n < D_)          v = bq[i * D_ + n];
    else if (n < 2 * D_) v = bk[i * D_ + n - D_];
    else                 v = bv[i * D_ + n - 2 * D_];
    bqkv[idx] = v;
}

// ---------------- embedding / prompt ----------------
__global__ void embed_kernel(const int* __restrict__ tok, const float* __restrict__ gp,
                             const float* __restrict__ temb, const float* __restrict__ pemb,
                             float* __restrict__ x) {
    int idx = blockIdx.x * blockDim.x + threadIdx.x;
    int d  = idx & (D_ - 1);
    int bs = idx >> 9;
    int s  = bs % S_;
    int b  = bs / S_;
    float v;
    if (s == 0)            v = temb[(size_t)tok[b * T_] * D_ + d];
    else if (s <= NP_)     v = gp[((size_t)b * DG_) * NP_ * D_ + (s - 1) * D_ + d];
    else                   v = temb[(size_t)tok[b * T_ + (s - NP_)] * D_ + d];
    x[idx] = v + pemb[s * D_ + d];
}

__global__ void prompt_kernel(const float* __restrict__ p, int bstride,
                              float* __restrict__ x) {
    int idx = blockIdx.x * blockDim.x + threadIdx.x;
    int d  = idx & (D_ - 1);
    int r  = idx >> 9;
    int ps = r % NP_;
    int b  = r / NP_;
    x[((size_t)(b * S_ + 1 + ps)) * D_ + d] = p[(size_t)b * bstride + ps * D_ + d];
}

// ---------------- layernorm -> bf16 hi/lo split ----------------
__device__ __forceinline__ float2 block_sum2(float s, float ss) {
    __shared__ float sh1[4], sh2[4];
    int lane = threadIdx.x & 31, w = threadIdx.x >> 5;
    #pragma unroll
    for (int o = 16; o > 0; o >>= 1) {
        s  += __shfl_down_sync(0xffffffffu, s,  o);
        ss += __shfl_down_sync(0xffffffffu, ss, o);
    }
    if (lane == 0) { sh1[w] = s; sh2[w] = ss; }
    __syncthreads();
    return make_float2(sh1[0] + sh1[1] + sh1[2] + sh1[3],
                       sh2[0] + sh2[1] + sh2[2] + sh2[3]);
}

__global__ void __launch_bounds__(128)
ln_split_kernel(const float* __restrict__ x, const float* __restrict__ g,
                const float* __restrict__ bb,
                bf16* __restrict__ hi, bf16* __restrict__ lo) {
    int row = blockIdx.x, tid = threadIdx.x;
    float4 vv = ((const float4*)(x + (size_t)row * D_))[tid];
    float s  = vv.x + vv.y + vv.z + vv.w;
    float ss = vv.x * vv.x + vv.y * vv.y + vv.z * vv.z + vv.w * vv.w;
    float2 tot = block_sum2(s, ss);
    float mean = tot.x * (1.0f / D_);
    float var  = tot.y * (1.0f / D_) - mean * mean;
    float rstd = rsqrtf(var + 1e-5f);
    float4 gv = ((const float4*)g)[tid];
    float4 bv = ((const float4*)bb)[tid];
    float4 ov;
    ov.x = (vv.x - mean) * rstd * gv.x + bv.x;
    ov.y = (vv.y - mean) * rstd * gv.y + bv.y;
    ov.z = (vv.z - mean) * rstd * gv.z + bv.z;
    ov.w = (vv.w - mean) * rstd * gv.w + bv.w;
    size_t o = (size_t)row * D_ + tid * 4;
    __nv_bfloat162 h01 = __floats2bfloat162_rn(ov.x, ov.y);
    __nv_bfloat162 h23 = __floats2bfloat162_rn(ov.z, ov.w);
    *(__nv_bfloat162*)(hi + o)     = h01;
    *(__nv_bfloat162*)(hi + o + 2) = h23;
    float lx = ov.x - __low2float(h01);
    float ly = ov.y - __high2float(h01);
    float lz = ov.z - __low2float(h23);
    float lw = ov.w - __high2float(h23);
    *(__nv_bfloat162*)(lo + o)     = __floats2bfloat162_rn(lx, ly);
    *(__nv_bfloat162*)(lo + o + 2) = __floats2bfloat162_rn(lz, lw);
}

// ---------------- HMMA GEMM: 128x128x64 tiles, cp.async x3 stages, bf16x3 -----
// A: [M][K] row-major bf16 hi/lo.  B: [N][K] K-major bf16 hi/lo.  D = A @ B^T.
// MODE 0: +bias, scale cols<512 by 0.125, fp32 out     (QKV)
// MODE 1: +bias +residual, fp32 out                    (O-proj, FF-down)
// MODE 2: +bias, gelu, bf16 hi/lo out                  (FF-up)
constexpr int STAGE_BYTES = 65536;                 // Ahi|Alo|Bhi|Blo @ 16KB each
constexpr int GEMM_SMEM = 3 * STAGE_BYTES;         // 192KB

template<int MODE>
__global__ void __launch_bounds__(256)
gemm_mma(const bf16* __restrict__ Ahi, const bf16* __restrict__ Alo,
         const bf16* __restrict__ Bhi, const bf16* __restrict__ Blo,
         const float* __restrict__ bias, const float* __restrict__ res,
         float* __restrict__ Cf, bf16* __restrict__ Chi, bf16* __restrict__ Clo,
         int N, int K) {
    extern __shared__ __align__(128) char smraw[];
    uint32_t sb = smem_u32(smraw);

    int tid = threadIdx.x, wid = tid >> 5, lane = tid & 31;
    int wm = wid >> 2, wn = wid & 3;               // warp tile: 64(M) x 32(N)
    int m0 = blockIdx.y * 128, n0 = blockIdx.x * 128;

    float acc[4][4][4];
    #pragma unroll
    for (int i = 0; i < 4; i++)
        #pragma unroll
        for (int j = 0; j < 4; j++)
            #pragma unroll
            for (int r = 0; r < 4; r++) acc[i][j][r] = 0.0f;

    const int nk = K >> 6;

    auto load_stage = [&](int buf, int kt2) {
        int k0 = kt2 << 6;
        uint32_t sb0 = sb + buf * STAGE_BYTES;
        #pragma unroll
        for (int t = 0; t < 4; t++) {
            int idx = tid + t * 256;               // 0..1023
            int row = idx >> 3, u = idx & 7;
            int pu = u ^ (row & 7);
            uint32_t so = sb0 + (row << 7) + (pu << 4);
            size_t ea = (size_t)(m0 + row) * K + k0 + u * 8;
            size_t eb = (size_t)(n0 + row) * K + k0 + u * 8;
            CP16(so,          Ahi + ea);
            CP16(so + 16384,  Alo + ea);
            CP16(so + 32768,  Bhi + eb);
            CP16(so + 49152,  Blo + eb);
        }
    };

    load_stage(0, 0); CP_COMMIT();
    load_stage(1, 1); CP_COMMIT();

    int lr = lane & 15, lu = lane >> 4;
    int bnn = wn * 32 + ((lane >> 4) << 3) + (lane & 7);
    int bus = (lane >> 3) & 1;

    for (int kt = 0; kt < nk; kt++) {
        if (kt < nk - 1) CP_WAIT1(); else CP_WAIT0();
        __syncthreads();
        if (kt + 2 < nk) { load_stage((kt + 2) % 3, kt + 2); CP_COMMIT(); }

        uint32_t base = sb + (kt % 3) * STAGE_BYTES;
        #pragma unroll
        for (int kk = 0; kk < 4; kk++) {           // four k16 steps in BK=64
            uint32_t aH[4][4], aL[4][4], bH[2][4], bL[2][4];
            #pragma unroll
            for (int mf = 0; mf < 4; mf++) {
                int r = wm * 64 + mf * 16 + lr;
                int u = kk * 2 + lu;
                uint32_t ad = base + (r << 7) + (((u ^ (r & 7))) << 4);
                ldsm4(aH[mf], ad);
                ldsm4(aL[mf], ad + 16384);
            }
            #pragma unroll
            for (int j = 0; j < 2; j++) {
                int n = bnn + j * 16;
                int u = kk * 2 + bus;
                uint32_t bd = base + 32768 + (n << 7) + ((u ^ (n & 7)) << 4);
                ldsm4(bH[j], bd);
                ldsm4(bL[j], bd + 16384);
            }
            #pragma unroll
            for (int mf = 0; mf < 4; mf++)
                #pragma unroll
                for (int nf = 0; nf < 4; nf++) {
                    float* d = acc[mf][nf];
                    const uint32_t* bh = &bH[nf >> 1][(nf & 1) * 2];
                    const uint32_t* bl = &bL[nf >> 1][(nf & 1) * 2];
                    mma16816(d, aH[mf], bh);
                    mma16816(d, aH[mf], bl);
                    mma16816(d, aL[mf], bh);
                }
        }
        __syncthreads();
    }

    // epilogue: write straight from accumulators
    int r0b = m0 + wm * 64 + (lane >> 2);
    int cb  = n0 + wn * 32 + 2 * (lane & 3);
    #pragma unroll
    for (int mf = 0; mf < 4; mf++) {
        #pragma unroll
        for (int nf = 0; nf < 4; nf++) {
            int c = cb + nf * 8;
            float b0 = bias[c], b1 = bias[c + 1];
            #pragma unroll
            for (int half = 0; half < 2; half++) {
                int r = r0b + mf * 16 + half * 8;
                float v0 = acc[mf][nf][half * 2 + 0] + b0;
                float v1 = acc[mf][nf][half * 2 + 1] + b1;
                size_t off = (size_t)r * N + c;
                if (MODE == 0) {
                    float sc = (c < D_) ? 0.125f : 1.0f;
                    *(float2*)(Cf + off) = make_float2(v0 * sc, v1 * sc);
                } else if (MODE == 1) {
                    float2 rr = *(const float2*)(res + off);
                    *(float2*)(Cf + off) = make_float2(v0 + rr.x, v1 + rr.y);
                } else {
                    v0 = v0 / (1.0f + __expf(-1.702f * v0));
                    v1 = v1 / (1.0f + __expf(-1.702f * v1));
                    __nv_bfloat162 h = __floats2bfloat162_rn(v0, v1);
                    *(__nv_bfloat162*)(Chi + off) = h;
                    float l0 = v0 - __low2float(h);
                    float l1 = v1 - __high2float(h);
                    *(__nv_bfloat162*)(Clo + off) = __floats2bfloat162_rn(l0, l1);
                }
            }
        }
    }
}

// ---------------- fused attention: one block per (b, h) ----------------
__global__ void __launch_bounds__(256)
attn_kernel(const float* __restrict__ qkv, const int* __restrict__ amask,
            bf16* __restrict__ ohi, bf16* __restrict__ olo) {
    __shared__ float sK[S_][DH_ + 1];
    __shared__ float sV[S_][DH_ + 1];
    __shared__ float sQ[8][DH_];
    __shared__ float sP[8][S_ + 3];
    __shared__ int   sM[S_];
    int h = blockIdx.x, b = blockIdx.y;
    int tid = threadIdx.x, lane = tid & 31, w = tid >> 5;

    for (int i = tid; i < S_ * DH_; i += 256) {
        int s = i >> 6, d = i & 63;
        size_t base = ((size_t)(b * S_ + s)) * QKVN + h * DH_ + d;
        sK[s][d] = qkv[base + D_];
        sV[s][d] = qkv[base + 2 * D_];
    }
    for (int i = tid; i < S_; i += 256)
        sM[i] = (i < NP_) ? 1 : amask[b * T_ + i - NP_];
    __syncthreads();

    for (int qi = w; qi < S_; qi += 8) {
        size_t qoff = ((size_t)(b * S_ + qi)) * QKVN + h * DH_;
        sQ[w][lane]      = qkv[qoff + lane];
        sQ[w][lane + 32] = qkv[qoff + lane + 32];
        __syncwarp();
        int nj = qi + 1;
        float sc[3];
        #pragma unroll
        for (int t = 0; t < 3; t++) {
            int j = lane + 32 * t;
            float dsum = -3.0e38f;
            if (j < nj) {
                dsum = 0.0f;
                #pragma unroll
                for (int dd = 0; dd < DH_; dd++) dsum += sQ[w][dd] * sK[j][dd];
                if (sM[j] == 0) dsum = -1.0e30f;
            }
            sc[t] = dsum;
        }
        float m = fmaxf(sc[0], fmaxf(sc[1], sc[2]));
        #pragma unroll
        for (int o2 = 16; o2 > 0; o2 >>= 1) m = fmaxf(m, __shfl_xor_sync(0xffffffffu, m, o2));
        float e[3], esum = 0.0f;
        #pragma unroll
        for (int t = 0; t < 3; t++) {
            int j = lane + 32 * t;
            e[t] = (j < nj) ? __expf(sc[t] - m) : 0.0f;
            esum += e[t];
        }
        #pragma unroll
        for (int o2 = 16; o2 > 0; o2 >>= 1) esum += __shfl_xor_sync(0xffffffffu, esum, o2);
        float inv = 1.0f / esum;
        #pragma unroll
        for (int t = 0; t < 3; t++) {
            int j = lane + 32 * t;
            if (j < nj) sP[w][j] = e[t] * inv;
        }
        __syncwarp();
        float a0 = 0.0f, a1 = 0.0f;
        for (int j = 0; j < nj; j++) {
            float p = sP[w][j];
            a0 += p * sV[j][lane];
            a1 += p * sV[j][lane + 32];
        }
        size_t ooff = ((size_t)(b * S_ + qi)) * D_ + h * DH_;
        bf16 h0 = __float2bfloat16(a0);
        ohi[ooff + lane] = h0;
        olo[ooff + lane] = __float2bfloat16(a0 - __bfloat162float(h0));
        bf16 h1 = __float2bfloat16(a1);
        ohi[ooff + lane + 32] = h1;
        olo[ooff + lane + 32] = __float2bfloat16(a1 - __bfloat162float(h1));
        __syncwarp();
    }
}

// ---------------- final: argmax gather + layernorm -> out ----------------
__global__ void __launch_bounds__(128)
final_kernel(const float* __restrict__ x, const int* __restrict__ tok,
             const float* __restrict__ g, const float* __restrict__ bb,
             float* __restrict__ out) {
    int b = blockIdx.x, tid = threadIdx.x;
    __shared__ int sval[128];
    __shared__ int srow;
    sval[tid] = (tid < T_) ? tok[b * T_ + tid] : (-2147483647 - 1);
    __syncthreads();
    if (tid == 0) {
        int best = sval[0], bi = 0;
        for (int t = 1; t < T_; t++)
            if (sval[t] > best) { best = sval[t]; bi = t; }
        srow = bi + NP_;
    }
    __syncthreads();
    int row = b * S_ + srow;
    float4 vv = ((const float4*)(x + (size_t)row * D_))[tid];
    float s  = vv.x + vv.y + vv.z + vv.w;
    float ss = vv.x * vv.x + vv.y * vv.y + vv.z * vv.z + vv.w * vv.w;
    float2 tot = block_sum2(s, ss);
    float mean = tot.x * (1.0f / D_);
    float var  = tot.y * (1.0f / D_) - mean * mean;
    float rstd = rsqrtf(var + 1e-5f);
    float4 gv = ((const float4*)g)[tid];
    float4 bv = ((const float4*)bb)[tid];
    float4 ov;
    ov.x = (vv.x - mean) * rstd * gv.x + bv.x;
    ov.y = (vv.y - mean) * rstd * gv.y + bv.y;
    ov.z = (vv.z - mean) * rstd * gv.z + bv.z;
    ov.w = (vv.w - mean) * rstd * gv.w + bv.w;
    ((float4*)(out + (size_t)b * D_))[tid] = ov;
}

// ---------------- launch ----------------
extern "C" void kernel_launch(void* const* d_in, const int* in_sizes, int n_in,
                              void* d_out, int out_size) {
    (void)in_sizes; (void)n_in; (void)out_size;
    const int*   tok   = (const int*)  d_in[0];
    const int*   amask = (const int*)  d_in[1];
    const float* gp    = (const float*)d_in[2];
    const float* sp    = (const float*)d_in[3];
    const float* temb  = (const float*)d_in[4];
    const float* pemb  = (const float*)d_in[5];
    const float* ln1g  = (const float*)d_in[6];
    const float* ln1b  = (const float*)d_in[7];
    const float* Wq    = (const float*)d_in[8];
    const float* bq    = (const float*)d_in[9];
    const float* Wk    = (const float*)d_in[10];
    const float* bk    = (const float*)d_in[11];
    const float* Wv    = (const float*)d_in[12];
    const float* bv    = (const float*)d_in[13];
    const float* Wo    = (const float*)d_in[14];
    const float* bo    = (const float*)d_in[15];
    const float* ln2g  = (const float*)d_in[16];
    const float* ln2b  = (const float*)d_in[17];
    const float* W1    = (const float*)d_in[18];
    const float* b1    = (const float*)d_in[19];
    const float* W2    = (const float*)d_in[20];
    const float* b2    = (const float*)d_in[21];
    const float* lnfg  = (const float*)d_in[22];
    const float* lnfb  = (const float*)d_in[23];
    float* out = (float*)d_out;

    float *x, *qkv, *bqkv;
    bf16 *hhi, *hlo, *ohi, *olo, *fhi, *flo;
    bf16 *wqh, *wql, *woh, *wol, *w1h, *w1l, *w2h, *w2l;
    cudaGetSymbolAddress((void**)&x,   g_x);
    cudaGetSymbolAddress((void**)&hhi, g_hhi);
    cudaGetSymbolAddress((void**)&hlo, g_hlo);
    cudaGetSymbolAddress((void**)&qkv, g_qkv);
    cudaGetSymbolAddress((void**)&ohi, g_ohi);
    cudaGetSymbolAddress((void**)&olo, g_olo);
    cudaGetSymbolAddress((void**)&fhi, g_fhi);
    cudaGetSymbolAddress((void**)&flo, g_flo);
    cudaGetSymbolAddress((void**)&wqh, w_qkv_hi);
    cudaGetSymbolAddress((void**)&wql, w_qkv_lo);
    cudaGetSymbolAddress((void**)&woh, w_o_hi);
    cudaGetSymbolAddress((void**)&wol, w_o_lo);
    cudaGetSymbolAddress((void**)&w1h, w_1_hi);
    cudaGetSymbolAddress((void**)&w1l, w_1_lo);
    cudaGetSymbolAddress((void**)&w2h, w_2_hi);
    cudaGetSymbolAddress((void**)&w2l, w_2_lo);
    cudaGetSymbolAddress((void**)&bqkv, g_bqkv);

    cudaFuncSetAttribute(gemm_mma<0>, cudaFuncAttributeMaxDynamicSharedMemorySize, GEMM_SMEM);
    cudaFuncSetAttribute(gemm_mma<1>, cudaFuncAttributeMaxDynamicSharedMemorySize, GEMM_SMEM);
    cudaFuncSetAttribute(gemm_mma<2>, cudaFuncAttributeMaxDynamicSharedMemorySize, GEMM_SMEM);

    // weight transpose + hi/lo split (once per launch)
    {
        dim3 thr(256);
        tsplit_kernel<<<dim3(16, 16, NL_), thr>>>(Wq, wqh,               wql,               D_, D_, (size_t)D_ * D_, (size_t)QKVN * D_);
        tsplit_kernel<<<dim3(16, 16, NL_), thr>>>(Wk, wqh + D_ * D_,     wql + D_ * D_,     D_, D_, (size_t)D_ * D_, (size_t)QKVN * D_);
        tsplit_kernel<<<dim3(16, 16, NL_), thr>>>(Wv, wqh + 2 * D_ * D_, wql + 2 * D_ * D_, D_, D_, (size_t)D_ * D_, (size_t)QKVN * D_);
        tsplit_kernel<<<dim3(16, 16, NL_), thr>>>(Wo, woh, wol, D_, D_,  (size_t)D_ * D_,  (size_t)D_ * D_);
        tsplit_kernel<<<dim3(64, 16, NL_), thr>>>(W1, w1h, w1l, D_, FF_, (size_t)D_ * FF_, (size_t)FF_ * D_);
        tsplit_kernel<<<dim3(16, 64, NL_), thr>>>(W2, w2h, w2l, FF_, D_, (size_t)FF_ * D_, (size_t)D_ * FF_);
        pack_bias_kernel<<<(NL_ * QKVN + 255) / 256, 256>>>(bq, bk, bv, bqkv);
    }

    embed_kernel<<<(B_ * S_ * D_) / 256, 256>>>(tok, gp, temb, pemb, x);

    dim3 gQKV(QKVN / 128, MROWS / 128);   // (12, 77)
    dim3 gD  (D_   / 128, MROWS / 128);   // (4, 77)
    dim3 gFF (FF_  / 128, MROWS / 128);   // (16, 77)

    for (int i = 0; i < NL_; i++) {
        if (i > 0) {
            const float* p; int bs;
            if (i < DG_) { p = gp + (size_t)i * NP_ * D_;                 bs = DG_ * NP_ * D_; }
            else         { p = sp + (size_t)(i - (NL_ - DS_)) * NP_ * D_; bs = DS_ * NP_ * D_; }
            prompt_kernel<<<(B_ * NP_ * D_) / 256, 256>>>(p, bs, x);
        }
        ln_split_kernel<<<MROWS, 128>>>(x, ln1g + i * D_, ln1b + i * D_, hhi, hlo);
        gemm_mma<0><<<gQKV, 256, GEMM_SMEM>>>(hhi, hlo,
            wqh + (size_t)i * QKVN * D_, wql + (size_t)i * QKVN * D_,
            bqkv + i * QKVN, nullptr, qkv, nullptr, nullptr, QKVN, D_);
        attn_kernel<<<dim3(H_, B_), 256>>>(qkv, amask, ohi, olo);
        gemm_mma<1><<<gD, 256, GEMM_SMEM>>>(ohi, olo,
            woh + (size_t)i * D_ * D_, wol + (size_t)i * D_ * D_,
            bo + i * D_, x, x, nullptr, nullptr, D_, D_);
        ln_split_kernel<<<MROWS, 128>>>(x, ln2g + i * D_, ln2b + i * D_, hhi, hlo);
        gemm_mma<2><<<gFF, 256, GEMM_SMEM>>>(hhi, hlo,
            w1h + (size_t)i * FF_ * D_, w1l + (size_t)i * FF_ * D_,
            b1 + i * FF_, nullptr, nullptr, fhi, flo, FF_, D_);
        gemm_mma<1><<<gD, 256, GEMM_SMEM>>>(fhi, flo,
            w2h + (size_t)i * D_ * FF_, w2l + (size_t)i * D_ * FF_,
            b2 + i * D_, x, x, nullptr, nullptr, D_, FF_);
    }
    final_kernel<<<B_, 128>>>(x, tok, lnfg, lnfb, out);
}

// round 5
// speedup vs baseline: 6.1961x; 1.0801x over previous
#include <cuda_runtime.h>
#include <cuda_bf16.h>
#include <math.h>
#include <stdint.h>

typedef __nv_bfloat16 bf16;

// ---------------- problem constants ----------------
constexpr int B_  = 128;
constexpr int T_  = 69;
constexpr int S_  = 77;
constexpr int D_  = 512;
constexpr int H_  = 8;
constexpr int DH_ = 64;
constexpr int NL_ = 12;
constexpr int FF_ = 2048;
constexpr int NP_ = 8;
constexpr int DG_ = 6;
constexpr int DS_ = 6;
constexpr int MROWS = B_ * S_;   // 9856 = 77 * 128
constexpr int QKVN  = 3 * D_;    // 1536

// ---------------- scratch (device globals; no runtime alloc) ----------------
__device__ __align__(128) float g_x  [MROWS * D_];
__device__ __align__(128) bf16  g_hhi[MROWS * D_];
__device__ __align__(128) bf16  g_hlo[MROWS * D_];
__device__ __align__(128) float g_qkv[MROWS * QKVN];
__device__ __align__(128) bf16  g_ohi[MROWS * D_];
__device__ __align__(128) bf16  g_olo[MROWS * D_];
__device__ __align__(128) bf16  g_fhi[MROWS * FF_];
__device__ __align__(128) bf16  g_flo[MROWS * FF_];

// transposed weight splits [layer][N][K] (K-major)
__device__ __align__(128) bf16  w_qkv_hi[NL_ * QKVN * D_];
__device__ __align__(128) bf16  w_qkv_lo[NL_ * QKVN * D_];
__device__ __align__(128) bf16  w_o_hi  [NL_ * D_ * D_];
__device__ __align__(128) bf16  w_o_lo  [NL_ * D_ * D_];
__device__ __align__(128) bf16  w_1_hi  [NL_ * FF_ * D_];
__device__ __align__(128) bf16  w_1_lo  [NL_ * FF_ * D_];
__device__ __align__(128) bf16  w_2_hi  [NL_ * D_ * FF_];
__device__ __align__(128) bf16  w_2_lo  [NL_ * D_ * FF_];
__device__ float g_bqkv  [NL_ * QKVN];

// ---------------- PTX helpers ----------------
__device__ __forceinline__ uint32_t smem_u32(const void* p) {
    uint32_t a;
    asm("{ .reg .u64 t; cvta.to.shared.u64 t, %1; cvt.u32.u64 %0, t; }" : "=r"(a) : "l"(p));
    return a;
}

#define CP16(saddr, gptr) \
    asm volatile("cp.async.cg.shared.global [%0], [%1], 16;" :: "r"(saddr), "l"(gptr) : "memory")
#define CP_COMMIT() asm volatile("cp.async.commit_group;" ::: "memory")
#define CP_WAIT1()  asm volatile("cp.async.wait_group 1;" ::: "memory")
#define CP_WAIT0()  asm volatile("cp.async.wait_group 0;" ::: "memory")

__device__ __forceinline__ void ldsm4(uint32_t* r, uint32_t addr) {
    asm volatile("ldmatrix.sync.aligned.m8n8.x4.shared.b16 {%0,%1,%2,%3}, [%4];"
                 : "=r"(r[0]), "=r"(r[1]), "=r"(r[2]), "=r"(r[3]) : "r"(addr));
}

__device__ __forceinline__ void mma16816(float* d, const uint32_t* a, const uint32_t* b) {
    asm volatile(
        "mma.sync.aligned.m16n8k16.row.col.f32.bf16.bf16.f32 "
        "{%0,%1,%2,%3}, {%4,%5,%6,%7}, {%8,%9}, {%0,%1,%2,%3};"
        : "+f"(d[0]), "+f"(d[1]), "+f"(d[2]), "+f"(d[3])
        : "r"(a[0]), "r"(a[1]), "r"(a[2]), "r"(a[3]), "r"(b[0]), "r"(b[1]));
}

// ---------------- unified preprocessing (1 launch) ----------------
// transpose+split 32x32 tile: out[n][k] = in[k][n]
__device__ __forceinline__ void tsplit_tile(const float* src, bf16* hi, bf16* lo,
                                            int K, int N, int n0, int k0) {
    __shared__ float t[32][33];
    int lx = threadIdx.x & 31, ly = threadIdx.x >> 5;
    #pragma unroll
    for (int i = ly; i < 32; i += 8)
        t[i][lx] = src[(size_t)(k0 + i) * N + n0 + lx];
    __syncthreads();
    #pragma unroll
    for (int i = ly; i < 32; i += 8) {
        float v = t[lx][i];
        size_t o = (size_t)(n0 + i) * K + k0 + lx;
        bf16 h = __float2bfloat16(v);
        hi[o] = h;
        lo[o] = __float2bfloat16(v - __bfloat162float(h));
    }
}

__global__ void __launch_bounds__(256)
prep_kernel(const float* __restrict__ Wq, const float* __restrict__ Wk,
            const float* __restrict__ Wv, const float* __restrict__ Wo,
            const float* __restrict__ W1, const float* __restrict__ W2,
            const float* __restrict__ bq, const float* __restrict__ bk,
            const float* __restrict__ bv,
            bf16* __restrict__ wqh, bf16* __restrict__ wql,
            bf16* __restrict__ woh, bf16* __restrict__ wol,
            bf16* __restrict__ w1h, bf16* __restrict__ w1l,
            bf16* __restrict__ w2h, bf16* __restrict__ w2l,
            float* __restrict__ bqkv) {
    int grp = blockIdx.y, layer = blockIdx.z, x = blockIdx.x;
    if (grp < 4) {                       // Wq/Wk/Wv/Wo : 512x512
        if (x >= 256) return;
        int nt = x & 15, kt = x >> 4;
        const float* src; bf16 *hi, *lo;
        size_t lsrc = (size_t)layer * D_ * D_;
        if (grp == 0)      { src = Wq + lsrc; hi = wqh + (size_t)layer * QKVN * D_;            lo = wql + (size_t)layer * QKVN * D_; }
        else if (grp == 1) { src = Wk + lsrc; hi = wqh + (size_t)layer * QKVN * D_ + D_ * D_;  lo = wql + (size_t)layer * QKVN * D_ + D_ * D_; }
        else if (grp == 2) { src = Wv + lsrc; hi = wqh + (size_t)layer * QKVN * D_ + 2*D_*D_;  lo = wql + (size_t)layer * QKVN * D_ + 2*D_*D_; }
        else               { src = Wo + lsrc; hi = woh + (size_t)layer * D_ * D_;              lo = wol + (size_t)layer * D_ * D_; }
        tsplit_tile(src, hi, lo, D_, D_, nt * 32, kt * 32);
    } else if (grp == 4) {               // W1 : [512][2048] -> [2048][512]
        int nt = x & 63, kt = x >> 6;
        tsplit_tile(W1 + (size_t)layer * D_ * FF_,
                    w1h + (size_t)layer * FF_ * D_, w1l + (size_t)layer * FF_ * D_,
                    D_, FF_, nt * 32, kt * 32);
    } else if (grp == 5) {               // W2 : [2048][512] -> [512][2048]
        int nt = x & 15, kt = x >> 4;
        tsplit_tile(W2 + (size_t)layer * FF_ * D_,
                    w2h + (size_t)layer * D_ * FF_, w2l + (size_t)layer * D_ * FF_,
                    FF_, D_, nt * 32, kt * 32);
    } else {                             // bias pack
        if (x >= 6) return;
        int idx = x * 256 + threadIdx.x;   // < QKVN
        int n = idx;
        float v;
        if (n < D_)          v = bq[layer * D_ + n];
        else if (n < 2 * D_) v = bk[layer * D_ + n - D_];
        else                 v = bv[layer * D_ + n - 2 * D_];
        bqkv[layer * QKVN + idx] = v;
    }
}

// ---------------- embedding / prompt ----------------
__global__ void embed_kernel(const int* __restrict__ tok, const float* __restrict__ gp,
                             const float* __restrict__ temb, const float* __restrict__ pemb,
                             float* __restrict__ x) {
    int idx = blockIdx.x * blockDim.x + threadIdx.x;
    int d  = idx & (D_ - 1);
    int bs = idx >> 9;
    int s  = bs % S_;
    int b  = bs / S_;
    float v;
    if (s == 0)            v = temb[(size_t)tok[b * T_] * D_ + d];
    else if (s <= NP_)     v = gp[((size_t)b * DG_) * NP_ * D_ + (s - 1) * D_ + d];
    else                   v = temb[(size_t)tok[b * T_ + (s - NP_)] * D_ + d];
    x[idx] = v + pemb[s * D_ + d];
}

__global__ void prompt_kernel(const float* __restrict__ p, int bstride,
                              float* __restrict__ x) {
    int idx = blockIdx.x * blockDim.x + threadIdx.x;
    int d  = idx & (D_ - 1);
    int r  = idx >> 9;
    int ps = r % NP_;
    int b  = r / NP_;
    x[((size_t)(b * S_ + 1 + ps)) * D_ + d] = p[(size_t)b * bstride + ps * D_ + d];
}

// ---------------- layernorm -> bf16 hi/lo split ----------------
__device__ __forceinline__ float2 block_sum2(float s, float ss) {
    __shared__ float sh1[4], sh2[4];
    int lane = threadIdx.x & 31, w = threadIdx.x >> 5;
    #pragma unroll
    for (int o = 16; o > 0; o >>= 1) {
        s  += __shfl_down_sync(0xffffffffu, s,  o);
        ss += __shfl_down_sync(0xffffffffu, ss, o);
    }
    if (lane == 0) { sh1[w] = s; sh2[w] = ss; }
    __syncthreads();
    return make_float2(sh1[0] + sh1[1] + sh1[2] + sh1[3],
                       sh2[0] + sh2[1] + sh2[2] + sh2[3]);
}

__global__ void __launch_bounds__(128)
ln_split_kernel(const float* __restrict__ x, const float* __restrict__ g,
                const float* __restrict__ bb,
                bf16* __restrict__ hi, bf16* __restrict__ lo) {
    int row = blockIdx.x, tid = threadIdx.x;
    float4 vv = ((const float4*)(x + (size_t)row * D_))[tid];
    float s  = vv.x + vv.y + vv.z + vv.w;
    float ss = vv.x * vv.x + vv.y * vv.y + vv.z * vv.z + vv.w * vv.w;
    float2 tot = block_sum2(s, ss);
    float mean = tot.x * (1.0f / D_);
    float var  = tot.y * (1.0f / D_) - mean * mean;
    float rstd = rsqrtf(var + 1e-5f);
    float4 gv = ((const float4*)g)[tid];
    float4 bv = ((const float4*)bb)[tid];
    float4 ov;
    ov.x = (vv.x - mean) * rstd * gv.x + bv.x;
    ov.y = (vv.y - mean) * rstd * gv.y + bv.y;
    ov.z = (vv.z - mean) * rstd * gv.z + bv.z;
    ov.w = (vv.w - mean) * rstd * gv.w + bv.w;
    size_t o = (size_t)row * D_ + tid * 4;
    __nv_bfloat162 h01 = __floats2bfloat162_rn(ov.x, ov.y);
    __nv_bfloat162 h23 = __floats2bfloat162_rn(ov.z, ov.w);
    *(__nv_bfloat162*)(hi + o)     = h01;
    *(__nv_bfloat162*)(hi + o + 2) = h23;
    float lx = ov.x - __low2float(h01);
    float ly = ov.y - __high2float(h01);
    float lz = ov.z - __low2float(h23);
    float lw = ov.w - __high2float(h23);
    *(__nv_bfloat162*)(lo + o)     = __floats2bfloat162_rn(lx, ly);
    *(__nv_bfloat162*)(lo + o + 2) = __floats2bfloat162_rn(lz, lw);
}

// ---------------- shared epilogue ----------------
template<int MODE>
__device__ __forceinline__ void epi_write(float v0, float v1, size_t off, int c,
                                          const float* bias, const float* res,
                                          float* Cf, bf16* Chi, bf16* Clo) {
    v0 += bias[c]; v1 += bias[c + 1];
    if (MODE == 0) {
        float sc = (c < D_) ? 0.125f : 1.0f;
        *(float2*)(Cf + off) = make_float2(v0 * sc, v1 * sc);
    } else if (MODE == 1) {
        float2 rr = *(const float2*)(res + off);
        *(float2*)(Cf + off) = make_float2(v0 + rr.x, v1 + rr.y);
    } else {
        v0 = v0 / (1.0f + __expf(-1.702f * v0));
        v1 = v1 / (1.0f + __expf(-1.702f * v1));
        __nv_bfloat162 h = __floats2bfloat162_rn(v0, v1);
        *(__nv_bfloat162*)(Chi + off) = h;
        float l0 = v0 - __low2float(h);
        float l1 = v1 - __high2float(h);
        *(__nv_bfloat162*)(Clo + off) = __floats2bfloat162_rn(l0, l1);
    }
}

// ---------------- GEMM A: 128x128 tile, 512 threads (16 warps, 32x32 warp tile)
constexpr int STAGE_A = 65536;
constexpr int SMEM_A_TOT = 3 * STAGE_A;     // 192KB

template<int MODE>
__global__ void __launch_bounds__(512)
gemm_mma128(const bf16* __restrict__ Ahi, const bf16* __restrict__ Alo,
            const bf16* __restrict__ Bhi, const bf16* __restrict__ Blo,
            const float* __restrict__ bias, const float* __restrict__ res,
            float* __restrict__ Cf, bf16* __restrict__ Chi, bf16* __restrict__ Clo,
            int N, int K) {
    extern __shared__ __align__(128) char smraw[];
    uint32_t sb = smem_u32(smraw);

    int tid = threadIdx.x, wid = tid >> 5, lane = tid & 31;
    int wm = wid >> 2, wn = wid & 3;           // 4x4 warp grid, 32x32 tiles
    int m0 = blockIdx.y * 128, n0 = blockIdx.x * 128;

    float acc[2][4][4];
    #pragma unroll
    for (int i = 0; i < 2; i++)
        #pragma unroll
        for (int j = 0; j < 4; j++)
            #pragma unroll
            for (int r = 0; r < 4; r++) acc[i][j][r] = 0.0f;

    const int nk = K >> 6;

    auto load_stage = [&](int buf, int kt2) {
        int k0 = kt2 << 6;
        uint32_t sb0 = sb + buf * STAGE_A;
        #pragma unroll
        for (int t = 0; t < 2; t++) {
            int idx = tid + t * 512;           // 0..1023 : A rows
            int row = idx >> 3, u = idx & 7;
            uint32_t so = sb0 + (row << 7) + ((u ^ (row & 7)) << 4);
            size_t ea = (size_t)(m0 + row) * K + k0 + u * 8;
            CP16(so,         Ahi + ea);
            CP16(so + 16384, Alo + ea);
        }
        #pragma unroll
        for (int t = 0; t < 2; t++) {
            int idx = tid + t * 512;           // B rows
            int row = idx >> 3, u = idx & 7;
            uint32_t so = sb0 + 32768 + (row << 7) + ((u ^ (row & 7)) << 4);
            size_t eb = (size_t)(n0 + row) * K + k0 + u * 8;
            CP16(so,         Bhi + eb);
            CP16(so + 16384, Blo + eb);
        }
    };

    load_stage(0, 0); CP_COMMIT();
    load_stage(1, 1); CP_COMMIT();

    int lr = lane & 15, lu = lane >> 4;
    int bnn = wn * 32 + ((lane >> 4) << 3) + (lane & 7);
    int bus = (lane >> 3) & 1;

    for (int kt = 0; kt < nk; kt++) {
        if (kt < nk - 1) CP_WAIT1(); else CP_WAIT0();
        __syncthreads();
        if (kt + 2 < nk) { load_stage((kt + 2) % 3, kt + 2); CP_COMMIT(); }

        uint32_t base = sb + (kt % 3) * STAGE_A;
        #pragma unroll
        for (int kk = 0; kk < 4; kk++) {
            uint32_t aH[2][4], aL[2][4], bH[2][4], bL[2][4];
            #pragma unroll
            for (int mf = 0; mf < 2; mf++) {
                int r = wm * 32 + mf * 16 + lr;
                int u = kk * 2 + lu;
                uint32_t ad = base + (r << 7) + ((u ^ (r & 7)) << 4);
                ldsm4(aH[mf], ad);
                ldsm4(aL[mf], ad + 16384);
            }
            #pragma unroll
            for (int j = 0; j < 2; j++) {
                int n = bnn + j * 16;
                int u = kk * 2 + bus;
                uint32_t bd = base + 32768 + (n << 7) + ((u ^ (n & 7)) << 4);
                ldsm4(bH[j], bd);
                ldsm4(bL[j], bd + 16384);
            }
            #pragma unroll
            for (int mf = 0; mf < 2; mf++)
                #pragma unroll
                for (int nf = 0; nf < 4; nf++) {
                    float* d = acc[mf][nf];
                    const uint32_t* bh = &bH[nf >> 1][(nf & 1) * 2];
                    const uint32_t* bl = &bL[nf >> 1][(nf & 1) * 2];
                    mma16816(d, aH[mf], bh);
                    mma16816(d, aH[mf], bl);
                    mma16816(d, aL[mf], bh);
                }
        }
    }

    int r0b = m0 + wm * 32 + (lane >> 2);
    int cb  = n0 + wn * 32 + 2 * (lane & 3);
    #pragma unroll
    for (int mf = 0; mf < 2; mf++)
        #pragma unroll
        for (int nf = 0; nf < 4; nf++) {
            int c = cb + nf * 8;
            #pragma unroll
            for (int half = 0; half < 2; half++) {
                int r = r0b + mf * 16 + half * 8;
                size_t off = (size_t)r * N + c;
                epi_write<MODE>(acc[mf][nf][half * 2], acc[mf][nf][half * 2 + 1],
                                off, c, bias, res, Cf, Chi, Clo);
            }
        }
}

// ---------------- GEMM B: 128x64 tile, 256 threads (8 warps, 32x32 warp tile)
constexpr int STAGE_B = 49152;
constexpr int SMEM_B_TOT = 3 * STAGE_B;     // 144KB

template<int MODE>
__global__ void __launch_bounds__(256)
gemm_mma64(const bf16* __restrict__ Ahi, const bf16* __restrict__ Alo,
           const bf16* __restrict__ Bhi, const bf16* __restrict__ Blo,
           const float* __restrict__ bias, const float* __restrict__ res,
           float* __restrict__ Cf, bf16* __restrict__ Chi, bf16* __restrict__ Clo,
           int N, int K) {
    extern __shared__ __align__(128) char smraw[];
    uint32_t sb = smem_u32(smraw);

    int tid = threadIdx.x, wid = tid >> 5, lane = tid & 31;
    int wm = wid >> 1, wn = wid & 1;           // 4x2 warp grid, 32x32 tiles
    int m0 = blockIdx.y * 128, n0 = blockIdx.x * 64;

    float acc[2][4][4];
    #pragma unroll
    for (int i = 0; i < 2; i++)
        #pragma unroll
        for (int j = 0; j < 4; j++)
            #pragma unroll
            for (int r = 0; r < 4; r++) acc[i][j][r] = 0.0f;

    const int nk = K >> 6;

    auto load_stage = [&](int buf, int kt2) {
        int k0 = kt2 << 6;
        uint32_t sb0 = sb + buf * STAGE_B;
        #pragma unroll
        for (int t = 0; t < 4; t++) {
            int idx = tid + t * 256;           // 0..1023 : A rows
            int row = idx >> 3, u = idx & 7;
            uint32_t so = sb0 + (row << 7) + ((u ^ (row & 7)) << 4);
            size_t ea = (size_t)(m0 + row) * K + k0 + u * 8;
            CP16(so,         Ahi + ea);
            CP16(so + 16384, Alo + ea);
        }
        #pragma unroll
        for (int t = 0; t < 2; t++) {
            int idx = tid + t * 256;           // 0..511 : B rows (64)
            int row = idx >> 3, u = idx & 7;
            uint32_t so = sb0 + 32768 + (row << 7) + ((u ^ (row & 7)) << 4);
            size_t eb = (size_t)(n0 + row) * K + k0 + u * 8;
            CP16(so,        Bhi + eb);
            CP16(so + 8192, Blo + eb);
        }
    };

    load_stage(0, 0); CP_COMMIT();
    load_stage(1, 1); CP_COMMIT();

    int lr = lane & 15, lu = lane >> 4;
    int bnn = wn * 32 + ((lane >> 4) << 3) + (lane & 7);
    int bus = (lane >> 3) & 1;

    for (int kt = 0; kt < nk; kt++) {
        if (kt < nk - 1) CP_WAIT1(); else CP_WAIT0();
        __syncthreads();
        if (kt + 2 < nk) { load_stage((kt + 2) % 3, kt + 2); CP_COMMIT(); }

        uint32_t base = sb + (kt % 3) * STAGE_B;
        #pragma unroll
        for (int kk = 0; kk < 4; kk++) {
            uint32_t aH[2][4], aL[2][4], bH[2][4], bL[2][4];
            #pragma unroll
            for (int mf = 0; mf < 2; mf++) {
                int r = wm * 32 + mf * 16 + lr;
                int u = kk * 2 + lu;
                uint32_t ad = base + (r << 7) + ((u ^ (r & 7)) << 4);
                ldsm4(aH[mf], ad);
                ldsm4(aL[mf], ad + 16384);
            }
            #pragma unroll
            for (int j = 0; j < 2; j++) {
                int n = bnn + j * 16;
                int u = kk * 2 + bus;
                uint32_t bd = base + 32768 + (n << 7) + ((u ^ (n & 7)) << 4);
                ldsm4(bH[j], bd);
                ldsm4(bL[j], bd + 8192);
            }
            #pragma unroll
            for (int mf = 0; mf < 2; mf++)
                #pragma unroll
                for (int nf = 0; nf < 4; nf++) {
                    float* d = acc[mf][nf];
                    const uint32_t* bh = &bH[nf >> 1][(nf & 1) * 2];
                    const uint32_t* bl = &bL[nf >> 1][(nf & 1) * 2];
                    mma16816(d, aH[mf], bh);
                    mma16816(d, aH[mf], bl);
                    mma16816(d, aL[mf], bh);
                }
        }
    }

    int r0b = m0 + wm * 32 + (lane >> 2);
    int cb  = n0 + wn * 32 + 2 * (lane & 3);
    #pragma unroll
    for (int mf = 0; mf < 2; mf++)
        #pragma unroll
        for (int nf = 0; nf < 4; nf++) {
            int c = cb + nf * 8;
            #pragma unroll
            for (int half = 0; half < 2; half++) {
                int r = r0b + mf * 16 + half * 8;
                size_t off = (size_t)r * N + c;
                epi_write<MODE>(acc[mf][nf][half * 2], acc[mf][nf][half * 2 + 1],
                                off, c, bias, res, Cf, Chi, Clo);
            }
        }
}

// ---------------- fused attention: one block per (b, h) ----------------
__global__ void __launch_bounds__(256)
attn_kernel(const float* __restrict__ qkv, const int* __restrict__ amask,
            bf16* __restrict__ ohi, bf16* __restrict__ olo) {
    __shared__ float sK[S_][DH_ + 1];
    __shared__ float sV[S_][DH_ + 1];
    __shared__ float sQ[8][DH_];
    __shared__ float sP[8][S_ + 3];
    __shared__ int   sM[S_];
    int h = blockIdx.x, b = blockIdx.y;
    int tid = threadIdx.x, lane = tid & 31, w = tid >> 5;

    for (int i = tid; i < S_ * DH_; i += 256) {
        int s = i >> 6, d = i & 63;
        size_t base = ((size_t)(b * S_ + s)) * QKVN + h * DH_ + d;
        sK[s][d] = qkv[base + D_];
        sV[s][d] = qkv[base + 2 * D_];
    }
    for (int i = tid; i < S_; i += 256)
        sM[i] = (i < NP_) ? 1 : amask[b * T_ + i - NP_];
    __syncthreads();

    for (int qi = w; qi < S_; qi += 8) {
        size_t qoff = ((size_t)(b * S_ + qi)) * QKVN + h * DH_;
        sQ[w][lane]      = qkv[qoff + lane];
        sQ[w][lane + 32] = qkv[qoff + lane + 32];
        __syncwarp();
        int nj = qi + 1;
        float sc[3];
        #pragma unroll
        for (int t = 0; t < 3; t++) {
            int j = lane + 32 * t;
            float dsum = -3.0e38f;
            if (j < nj) {
                dsum = 0.0f;
                #pragma unroll
                for (int dd = 0; dd < DH_; dd++) dsum += sQ[w][dd] * sK[j][dd];
                if (sM[j] == 0) dsum = -1.0e30f;
            }
            sc[t] = dsum;
        }
        float m = fmaxf(sc[0], fmaxf(sc[1], sc[2]));
        #pragma unroll
        for (int o2 = 16; o2 > 0; o2 >>= 1) m = fmaxf(m, __shfl_xor_sync(0xffffffffu, m, o2));
        float e[3], esum = 0.0f;
        #pragma unroll
        for (int t = 0; t < 3; t++) {
            int j = lane + 32 * t;
            e[t] = (j < nj) ? __expf(sc[t] - m) : 0.0f;
            esum += e[t];
        }
        #pragma unroll
        for (int o2 = 16; o2 > 0; o2 >>= 1) esum += __shfl_xor_sync(0xffffffffu, esum, o2);
        float inv = 1.0f / esum;
        #pragma unroll
        for (int t = 0; t < 3; t++) {
            int j = lane + 32 * t;
            if (j < nj) sP[w][j] = e[t] * inv;
        }
        __syncwarp();
        float a0 = 0.0f, a1 = 0.0f;
        for (int j = 0; j < nj; j++) {
            float p = sP[w][j];
            a0 += p * sV[j][lane];
            a1 += p * sV[j][lane + 32];
        }
        size_t ooff = ((size_t)(b * S_ + qi)) * D_ + h * DH_;
        bf16 h0 = __float2bfloat16(a0);
        ohi[ooff + lane] = h0;
        olo[ooff + lane] = __float2bfloat16(a0 - __bfloat162float(h0));
        bf16 h1 = __float2bfloat16(a1);
        ohi[ooff + lane + 32] = h1;
        olo[ooff + lane + 32] = __float2bfloat16(a1 - __bfloat162float(h1));
        __syncwarp();
    }
}

// ---------------- final: argmax gather + layernorm -> out ----------------
__global__ void __launch_bounds__(128)
final_kernel(const float* __restrict__ x, const int* __restrict__ tok,
             const float* __restrict__ g, const float* __restrict__ bb,
             float* __restrict__ out) {
    int b = blockIdx.x, tid = threadIdx.x;
    __shared__ int sval[128];
    __shared__ int srow;
    sval[tid] = (tid < T_) ? tok[b * T_ + tid] : (-2147483647 - 1);
    __syncthreads();
    if (tid == 0) {
        int best = sval[0], bi = 0;
        for (int t = 1; t < T_; t++)
            if (sval[t] > best) { best = sval[t]; bi = t; }
        srow = bi + NP_;
    }
    __syncthreads();
    int row = b * S_ + srow;
    float4 vv = ((const float4*)(x + (size_t)row * D_))[tid];
    float s  = vv.x + vv.y + vv.z + vv.w;
    float ss = vv.x * vv.x + vv.y * vv.y + vv.z * vv.z + vv.w * vv.w;
    float2 tot = block_sum2(s, ss);
    float mean = tot.x * (1.0f / D_);
    float var  = tot.y * (1.0f / D_) - mean * mean;
    float rstd = rsqrtf(var + 1e-5f);
    float4 gv = ((const float4*)g)[tid];
    float4 bv = ((const float4*)bb)[tid];
    float4 ov;
    ov.x = (vv.x - mean) * rstd * gv.x + bv.x;
    ov.y = (vv.y - mean) * rstd * gv.y + bv.y;
    ov.z = (vv.z - mean) * rstd * gv.z + bv.z;
    ov.w = (vv.w - mean) * rstd * gv.w + bv.w;
    ((float4*)(out + (size_t)b * D_))[tid] = ov;
}

// ---------------- launch ----------------
extern "C" void kernel_launch(void* const* d_in, const int* in_sizes, int n_in,
                              void* d_out, int out_size) {
    (void)in_sizes; (void)n_in; (void)out_size;
    const int*   tok   = (const int*)  d_in[0];
    const int*   amask = (const int*)  d_in[1];
    const float* gp    = (const float*)d_in[2];
    const float* sp    = (const float*)d_in[3];
    const float* temb  = (const float*)d_in[4];
    const float* pemb  = (const float*)d_in[5];
    const float* ln1g  = (const float*)d_in[6];
    const float* ln1b  = (const float*)d_in[7];
    const float* Wq    = (const float*)d_in[8];
    const float* bq    = (const float*)d_in[9];
    const float* Wk    = (const float*)d_in[10];
    const float* bk    = (const float*)d_in[11];
    const float* Wv    = (const float*)d_in[12];
    const float* bv    = (const float*)d_in[13];
    const float* Wo    = (const float*)d_in[14];
    const float* bo    = (const float*)d_in[15];
    const float* ln2g  = (const float*)d_in[16];
    const float* ln2b  = (const float*)d_in[17];
    const float* W1    = (const float*)d_in[18];
    const float* b1    = (const float*)d_in[19];
    const float* W2    = (const float*)d_in[20];
    const float* b2    = (const float*)d_in[21];
    const float* lnfg  = (const float*)d_in[22];
    const float* lnfb  = (const float*)d_in[23];
    float* out = (float*)d_out;

    float *x, *qkv, *bqkv;
    bf16 *hhi, *hlo, *ohi, *olo, *fhi, *flo;
    bf16 *wqh, *wql, *woh, *wol, *w1h, *w1l, *w2h, *w2l;
    cudaGetSymbolAddress((void**)&x,   g_x);
    cudaGetSymbolAddress((void**)&hhi, g_hhi);
    cudaGetSymbolAddress((void**)&hlo, g_hlo);
    cudaGetSymbolAddress((void**)&qkv, g_qkv);
    cudaGetSymbolAddress((void**)&ohi, g_ohi);
    cudaGetSymbolAddress((void**)&olo, g_olo);
    cudaGetSymbolAddress((void**)&fhi, g_fhi);
    cudaGetSymbolAddress((void**)&flo, g_flo);
    cudaGetSymbolAddress((void**)&wqh, w_qkv_hi);
    cudaGetSymbolAddress((void**)&wql, w_qkv_lo);
    cudaGetSymbolAddress((void**)&woh, w_o_hi);
    cudaGetSymbolAddress((void**)&wol, w_o_lo);
    cudaGetSymbolAddress((void**)&w1h, w_1_hi);
    cudaGetSymbolAddress((void**)&w1l, w_1_lo);
    cudaGetSymbolAddress((void**)&w2h, w_2_hi);
    cudaGetSymbolAddress((void**)&w2l, w_2_lo);
    cudaGetSymbolAddress((void**)&bqkv, g_bqkv);

    cudaFuncSetAttribute(gemm_mma128<0>, cudaFuncAttributeMaxDynamicSharedMemorySize, SMEM_A_TOT);
    cudaFuncSetAttribute(gemm_mma128<2>, cudaFuncAttributeMaxDynamicSharedMemorySize, SMEM_A_TOT);
    cudaFuncSetAttribute(gemm_mma64<1>,  cudaFuncAttributeMaxDynamicSharedMemorySize, SMEM_B_TOT);

    // 1: preprocessing (weights transpose+split, bias pack)
    prep_kernel<<<dim3(1024, 7, NL_), 256>>>(Wq, Wk, Wv, Wo, W1, W2, bq, bk, bv,
                                             wqh, wql, woh, wol, w1h, w1l, w2h, w2l, bqkv);
    // 2: embedding
    embed_kernel<<<(B_ * S_ * D_) / 256, 256>>>(tok, gp, temb, pemb, x);

    dim3 gQKV(QKVN / 128, MROWS / 128);   // (12, 77)
    dim3 gFF (FF_  / 128, MROWS / 128);   // (16, 77)
    dim3 gD64(D_   / 64,  MROWS / 128);   // (8, 77) = 616 CTAs

    for (int i = 0; i < NL_; i++) {
        if (i > 0) {
            const float* p; int bs;
            if (i < DG_) { p = gp + (size_t)i * NP_ * D_;                 bs = DG_ * NP_ * D_; }
            else         { p = sp + (size_t)(i - (NL_ - DS_)) * NP_ * D_; bs = DS_ * NP_ * D_; }
            prompt_kernel<<<(B_ * NP_ * D_) / 256, 256>>>(p, bs, x);
        }
        ln_split_kernel<<<MROWS, 128>>>(x, ln1g + i * D_, ln1b + i * D_, hhi, hlo);
        gemm_mma128<0><<<gQKV, 512, SMEM_A_TOT>>>(hhi, hlo,
            wqh + (size_t)i * QKVN * D_, wql + (size_t)i * QKVN * D_,
            bqkv + i * QKVN, nullptr, qkv, nullptr, nullptr, QKVN, D_);
        attn_kernel<<<dim3(H_, B_), 256>>>(qkv, amask, ohi, olo);
        gemm_mma64<1><<<gD64, 256, SMEM_B_TOT>>>(ohi, olo,
            woh + (size_t)i * D_ * D_, wol + (size_t)i * D_ * D_,
            bo + i * D_, x, x, nullptr, nullptr, D_, D_);
        ln_split_kernel<<<MROWS, 128>>>(x, ln2g + i * D_, ln2b + i * D_, hhi, hlo);
        gemm_mma128<2><<<gFF, 512, SMEM_A_TOT>>>(hhi, hlo,
            w1h + (size_t)i * FF_ * D_, w1l + (size_t)i * FF_ * D_,
            b1 + i * FF_, nullptr, nullptr, fhi, flo, FF_, D_);
        gemm_mma64<1><<<gD64, 256, SMEM_B_TOT>>>(fhi, flo,
            w2h + (size_t)i * D_ * FF_, w2l + (size_t)i * D_ * FF_,
            b2 + i * D_, x, x, nullptr, nullptr, D_, FF_);
    }
    final_kernel<<<B_, 128>>>(x, tok, lnfg, lnfb, out);
}

// round 6
// speedup vs baseline: 6.5547x; 1.0579x over previous
#include <cuda_runtime.h>
#include <cuda_bf16.h>
#include <math.h>
#include <stdint.h>

typedef __nv_bfloat16 bf16;

// ---------------- problem constants ----------------
constexpr int B_  = 128;
constexpr int T_  = 69;
constexpr int S_  = 77;
constexpr int D_  = 512;
constexpr int H_  = 8;
constexpr int DH_ = 64;
constexpr int NL_ = 12;
constexpr int FF_ = 2048;
constexpr int NP_ = 8;
constexpr int DG_ = 6;
constexpr int DS_ = 6;
constexpr int MROWS = B_ * S_;   // 9856 = 77 * 128
constexpr int QKVN  = 3 * D_;    // 1536

// ---------------- scratch (device globals; no runtime alloc) ----------------
__device__ __align__(128) float g_x  [MROWS * D_];
__device__ __align__(128) bf16  g_hhi[MROWS * D_];
__device__ __align__(128) bf16  g_hlo[MROWS * D_];
__device__ __align__(128) float g_qkv[MROWS * QKVN];
__device__ __align__(128) bf16  g_ohi[MROWS * D_];
__device__ __align__(128) bf16  g_olo[MROWS * D_];
__device__ __align__(128) bf16  g_fhi[MROWS * FF_];
__device__ __align__(128) bf16  g_flo[MROWS * FF_];

// transposed weight splits [layer][N][K] (K-major)
__device__ __align__(128) bf16  w_qkv_hi[NL_ * QKVN * D_];
__device__ __align__(128) bf16  w_qkv_lo[NL_ * QKVN * D_];
__device__ __align__(128) bf16  w_o_hi  [NL_ * D_ * D_];
__device__ __align__(128) bf16  w_o_lo  [NL_ * D_ * D_];
__device__ __align__(128) bf16  w_1_hi  [NL_ * FF_ * D_];
__device__ __align__(128) bf16  w_1_lo  [NL_ * FF_ * D_];
__device__ __align__(128) bf16  w_2_hi  [NL_ * D_ * FF_];
__device__ __align__(128) bf16  w_2_lo  [NL_ * D_ * FF_];
__device__ float g_bqkv  [NL_ * QKVN];

// ---------------- PTX helpers ----------------
__device__ __forceinline__ uint32_t smem_u32(const void* p) {
    uint32_t a;
    asm("{ .reg .u64 t; cvta.to.shared.u64 t, %1; cvt.u32.u64 %0, t; }" : "=r"(a) : "l"(p));
    return a;
}

#define CP16(saddr, gptr) \
    asm volatile("cp.async.cg.shared.global [%0], [%1], 16;" :: "r"(saddr), "l"(gptr) : "memory")
#define CP_COMMIT() asm volatile("cp.async.commit_group;" ::: "memory")
#define CP_WAIT1()  asm volatile("cp.async.wait_group 1;" ::: "memory")
#define CP_WAIT0()  asm volatile("cp.async.wait_group 0;" ::: "memory")

__device__ __forceinline__ void ldsm4(uint32_t* r, uint32_t addr) {
    asm volatile("ldmatrix.sync.aligned.m8n8.x4.shared.b16 {%0,%1,%2,%3}, [%4];"
                 : "=r"(r[0]), "=r"(r[1]), "=r"(r[2]), "=r"(r[3]) : "r"(addr));
}

__device__ __forceinline__ void mma16816(float* d, const uint32_t* a, const uint32_t* b) {
    asm volatile(
        "mma.sync.aligned.m16n8k16.row.col.f32.bf16.bf16.f32 "
        "{%0,%1,%2,%3}, {%4,%5,%6,%7}, {%8,%9}, {%0,%1,%2,%3};"
        : "+f"(d[0]), "+f"(d[1]), "+f"(d[2]), "+f"(d[3])
        : "r"(a[0]), "r"(a[1]), "r"(a[2]), "r"(a[3]), "r"(b[0]), "r"(b[1]));
}

// ---------------- unified preprocessing (1 launch) ----------------
__device__ __forceinline__ void tsplit_tile(const float* src, bf16* hi, bf16* lo,
                                            int K, int N, int n0, int k0) {
    __shared__ float t[32][33];
    int lx = threadIdx.x & 31, ly = threadIdx.x >> 5;
    #pragma unroll
    for (int i = ly; i < 32; i += 8)
        t[i][lx] = src[(size_t)(k0 + i) * N + n0 + lx];
    __syncthreads();
    #pragma unroll
    for (int i = ly; i < 32; i += 8) {
        float v = t[lx][i];
        size_t o = (size_t)(n0 + i) * K + k0 + lx;
        bf16 h = __float2bfloat16(v);
        hi[o] = h;
        lo[o] = __float2bfloat16(v - __bfloat162float(h));
    }
}

__global__ void __launch_bounds__(256)
prep_kernel(const float* __restrict__ Wq, const float* __restrict__ Wk,
            const float* __restrict__ Wv, const float* __restrict__ Wo,
            const float* __restrict__ W1, const float* __restrict__ W2,
            const float* __restrict__ bq, const float* __restrict__ bk,
            const float* __restrict__ bv,
            bf16* __restrict__ wqh, bf16* __restrict__ wql,
            bf16* __restrict__ woh, bf16* __restrict__ wol,
            bf16* __restrict__ w1h, bf16* __restrict__ w1l,
            bf16* __restrict__ w2h, bf16* __restrict__ w2l,
            float* __restrict__ bqkv) {
    int grp = blockIdx.y, layer = blockIdx.z, x = blockIdx.x;
    if (grp < 4) {
        if (x >= 256) return;
        int nt = x & 15, kt = x >> 4;
        const float* src; bf16 *hi, *lo;
        size_t lsrc = (size_t)layer * D_ * D_;
        if (grp == 0)      { src = Wq + lsrc; hi = wqh + (size_t)layer * QKVN * D_;            lo = wql + (size_t)layer * QKVN * D_; }
        else if (grp == 1) { src = Wk + lsrc; hi = wqh + (size_t)layer * QKVN * D_ + D_ * D_;  lo = wql + (size_t)layer * QKVN * D_ + D_ * D_; }
        else if (grp == 2) { src = Wv + lsrc; hi = wqh + (size_t)layer * QKVN * D_ + 2*D_*D_;  lo = wql + (size_t)layer * QKVN * D_ + 2*D_*D_; }
        else               { src = Wo + lsrc; hi = woh + (size_t)layer * D_ * D_;              lo = wol + (size_t)layer * D_ * D_; }
        tsplit_tile(src, hi, lo, D_, D_, nt * 32, kt * 32);
    } else if (grp == 4) {
        int nt = x & 63, kt = x >> 6;
        tsplit_tile(W1 + (size_t)layer * D_ * FF_,
                    w1h + (size_t)layer * FF_ * D_, w1l + (size_t)layer * FF_ * D_,
                    D_, FF_, nt * 32, kt * 32);
    } else if (grp == 5) {
        int nt = x & 15, kt = x >> 4;
        tsplit_tile(W2 + (size_t)layer * FF_ * D_,
                    w2h + (size_t)layer * D_ * FF_, w2l + (size_t)layer * D_ * FF_,
                    FF_, D_, nt * 32, kt * 32);
    } else {
        if (x >= 6) return;
        int idx = x * 256 + threadIdx.x;
        int n = idx;
        float v;
        if (n < D_)          v = bq[layer * D_ + n];
        else if (n < 2 * D_) v = bk[layer * D_ + n - D_];
        else                 v = bv[layer * D_ + n - 2 * D_];
        bqkv[layer * QKVN + idx] = v;
    }
}

// ---------------- embedding / prompt ----------------
__global__ void embed_kernel(const int* __restrict__ tok, const float* __restrict__ gp,
                             const float* __restrict__ temb, const float* __restrict__ pemb,
                             float* __restrict__ x) {
    int idx = blockIdx.x * blockDim.x + threadIdx.x;
    int d  = idx & (D_ - 1);
    int bs = idx >> 9;
    int s  = bs % S_;
    int b  = bs / S_;
    float v;
    if (s == 0)            v = temb[(size_t)tok[b * T_] * D_ + d];
    else if (s <= NP_)     v = gp[((size_t)b * DG_) * NP_ * D_ + (s - 1) * D_ + d];
    else                   v = temb[(size_t)tok[b * T_ + (s - NP_)] * D_ + d];
    x[idx] = v + pemb[s * D_ + d];
}

__global__ void prompt_kernel(const float* __restrict__ p, int bstride,
                              float* __restrict__ x) {
    int idx = blockIdx.x * blockDim.x + threadIdx.x;
    int d  = idx & (D_ - 1);
    int r  = idx >> 9;
    int ps = r % NP_;
    int b  = r / NP_;
    x[((size_t)(b * S_ + 1 + ps)) * D_ + d] = p[(size_t)b * bstride + ps * D_ + d];
}

// ---------------- layernorm -> bf16 hi/lo split ----------------
__device__ __forceinline__ float2 block_sum2(float s, float ss) {
    __shared__ float sh1[4], sh2[4];
    int lane = threadIdx.x & 31, w = threadIdx.x >> 5;
    #pragma unroll
    for (int o = 16; o > 0; o >>= 1) {
        s  += __shfl_down_sync(0xffffffffu, s,  o);
        ss += __shfl_down_sync(0xffffffffu, ss, o);
    }
    if (lane == 0) { sh1[w] = s; sh2[w] = ss; }
    __syncthreads();
    return make_float2(sh1[0] + sh1[1] + sh1[2] + sh1[3],
                       sh2[0] + sh2[1] + sh2[2] + sh2[3]);
}

__global__ void __launch_bounds__(128)
ln_split_kernel(const float* __restrict__ x, const float* __restrict__ g,
                const float* __restrict__ bb,
                bf16* __restrict__ hi, bf16* __restrict__ lo) {
    int row = blockIdx.x, tid = threadIdx.x;
    float4 vv = ((const float4*)(x + (size_t)row * D_))[tid];
    float s  = vv.x + vv.y + vv.z + vv.w;
    float ss = vv.x * vv.x + vv.y * vv.y + vv.z * vv.z + vv.w * vv.w;
    float2 tot = block_sum2(s, ss);
    float mean = tot.x * (1.0f / D_);
    float var  = tot.y * (1.0f / D_) - mean * mean;
    float rstd = rsqrtf(var + 1e-5f);
    float4 gv = ((const float4*)g)[tid];
    float4 bv = ((const float4*)bb)[tid];
    float4 ov;
    ov.x = (vv.x - mean) * rstd * gv.x + bv.x;
    ov.y = (vv.y - mean) * rstd * gv.y + bv.y;
    ov.z = (vv.z - mean) * rstd * gv.z + bv.z;
    ov.w = (vv.w - mean) * rstd * gv.w + bv.w;
    size_t o = (size_t)row * D_ + tid * 4;
    __nv_bfloat162 h01 = __floats2bfloat162_rn(ov.x, ov.y);
    __nv_bfloat162 h23 = __floats2bfloat162_rn(ov.z, ov.w);
    *(__nv_bfloat162*)(hi + o)     = h01;
    *(__nv_bfloat162*)(hi + o + 2) = h23;
    float lx = ov.x - __low2float(h01);
    float ly = ov.y - __high2float(h01);
    float lz = ov.z - __low2float(h23);
    float lw = ov.w - __high2float(h23);
    *(__nv_bfloat162*)(lo + o)     = __floats2bfloat162_rn(lx, ly);
    *(__nv_bfloat162*)(lo + o + 2) = __floats2bfloat162_rn(lz, lw);
}

// ---------------- shared epilogue ----------------
template<int MODE>
__device__ __forceinline__ void epi_write(float v0, float v1, size_t off, int c,
                                          const float* bias, const float* res,
                                          float* Cf, bf16* Chi, bf16* Clo) {
    v0 += bias[c]; v1 += bias[c + 1];
    if (MODE == 0) {
        float sc = (c < D_) ? 0.125f : 1.0f;
        *(float2*)(Cf + off) = make_float2(v0 * sc, v1 * sc);
    } else if (MODE == 1) {
        float2 rr = *(const float2*)(res + off);
        *(float2*)(Cf + off) = make_float2(v0 + rr.x, v1 + rr.y);
    } else {
        v0 = v0 / (1.0f + __expf(-1.702f * v0));
        v1 = v1 / (1.0f + __expf(-1.702f * v1));
        __nv_bfloat162 h = __floats2bfloat162_rn(v0, v1);
        *(__nv_bfloat162*)(Chi + off) = h;
        float l0 = v0 - __low2float(h);
        float l1 = v1 - __high2float(h);
        *(__nv_bfloat162*)(Clo + off) = __floats2bfloat162_rn(l0, l1);
    }
}

// term-major MMA issue: distance-8 between same-acc MMAs (hides HMMA latency)
#define MMA_BLOCK_TERMMAJOR()                                              \
    _Pragma("unroll")                                                      \
    for (int term = 0; term < 3; term++) {                                 \
        _Pragma("unroll")                                                  \
        for (int mf = 0; mf < 2; mf++) {                                   \
            _Pragma("unroll")                                              \
            for (int nf = 0; nf < 4; nf++) {                               \
                const uint32_t* a = (term == 2) ? aL[mf] : aH[mf];         \
                const uint32_t* b = (term == 1) ? &bL[nf >> 1][(nf & 1) * 2] \
                                                : &bH[nf >> 1][(nf & 1) * 2]; \
                mma16816(acc[mf][nf], a, b);                               \
            }                                                              \
        }                                                                  \
    }

// ---------------- GEMM A: 128x128 tile, 512 threads, 3-stage ----------------
constexpr int STAGE_A = 65536;
constexpr int SMEM_A_TOT = 3 * STAGE_A;     // 192KB

template<int MODE>
__global__ void __launch_bounds__(512)
gemm_mma128(const bf16* __restrict__ Ahi, const bf16* __restrict__ Alo,
            const bf16* __restrict__ Bhi, const bf16* __restrict__ Blo,
            const float* __restrict__ bias, const float* __restrict__ res,
            float* __restrict__ Cf, bf16* __restrict__ Chi, bf16* __restrict__ Clo,
            int N, int K) {
    extern __shared__ __align__(128) char smraw[];
    uint32_t sb = smem_u32(smraw);

    int tid = threadIdx.x, wid = tid >> 5, lane = tid & 31;
    int wm = wid >> 2, wn = wid & 3;
    int m0 = blockIdx.y * 128, n0 = blockIdx.x * 128;

    float acc[2][4][4];
    #pragma unroll
    for (int i = 0; i < 2; i++)
        #pragma unroll
        for (int j = 0; j < 4; j++)
            #pragma unroll
            for (int r = 0; r < 4; r++) acc[i][j][r] = 0.0f;

    const int nk = K >> 6;

    auto load_stage = [&](int buf, int kt2) {
        int k0 = kt2 << 6;
        uint32_t sb0 = sb + buf * STAGE_A;
        #pragma unroll
        for (int t = 0; t < 2; t++) {
            int idx = tid + t * 512;
            int row = idx >> 3, u = idx & 7;
            uint32_t so = sb0 + (row << 7) + ((u ^ (row & 7)) << 4);
            size_t ea = (size_t)(m0 + row) * K + k0 + u * 8;
            CP16(so,         Ahi + ea);
            CP16(so + 16384, Alo + ea);
        }
        #pragma unroll
        for (int t = 0; t < 2; t++) {
            int idx = tid + t * 512;
            int row = idx >> 3, u = idx & 7;
            uint32_t so = sb0 + 32768 + (row << 7) + ((u ^ (row & 7)) << 4);
            size_t eb = (size_t)(n0 + row) * K + k0 + u * 8;
            CP16(so,         Bhi + eb);
            CP16(so + 16384, Blo + eb);
        }
    };

    load_stage(0, 0); CP_COMMIT();
    load_stage(1, 1); CP_COMMIT();

    int lr = lane & 15, lu = lane >> 4;
    int bnn = wn * 32 + ((lane >> 4) << 3) + (lane & 7);
    int bus = (lane >> 3) & 1;

    for (int kt = 0; kt < nk; kt++) {
        if (kt < nk - 1) CP_WAIT1(); else CP_WAIT0();
        __syncthreads();
        if (kt + 2 < nk) { load_stage((kt + 2) % 3, kt + 2); CP_COMMIT(); }

        uint32_t base = sb + (kt % 3) * STAGE_A;
        #pragma unroll
        for (int kk = 0; kk < 4; kk++) {
            uint32_t aH[2][4], aL[2][4], bH[2][4], bL[2][4];
            #pragma unroll
            for (int mf = 0; mf < 2; mf++) {
                int r = wm * 32 + mf * 16 + lr;
                int u = kk * 2 + lu;
                uint32_t ad = base + (r << 7) + ((u ^ (r & 7)) << 4);
                ldsm4(aH[mf], ad);
                ldsm4(aL[mf], ad + 16384);
            }
            #pragma unroll
            for (int j = 0; j < 2; j++) {
                int n = bnn + j * 16;
                int u = kk * 2 + bus;
                uint32_t bd = base + 32768 + (n << 7) + ((u ^ (n & 7)) << 4);
                ldsm4(bH[j], bd);
                ldsm4(bL[j], bd + 16384);
            }
            MMA_BLOCK_TERMMAJOR();
        }
    }

    int r0b = m0 + wm * 32 + (lane >> 2);
    int cb  = n0 + wn * 32 + 2 * (lane & 3);
    #pragma unroll
    for (int mf = 0; mf < 2; mf++)
        #pragma unroll
        for (int nf = 0; nf < 4; nf++) {
            int c = cb + nf * 8;
            #pragma unroll
            for (int half = 0; half < 2; half++) {
                int r = r0b + mf * 16 + half * 8;
                size_t off = (size_t)r * N + c;
                epi_write<MODE>(acc[mf][nf][half * 2], acc[mf][nf][half * 2 + 1],
                                off, c, bias, res, Cf, Chi, Clo);
            }
        }
}

// ---------------- GEMM B: 128x64 tile, 256 threads, 2-stage, 2 CTAs/SM -------
constexpr int STAGE_B = 49152;
constexpr int SMEM_B_TOT = 2 * STAGE_B;     // 96KB -> 2 CTAs/SM

template<int MODE>
__global__ void __launch_bounds__(256, 2)
gemm_mma64(const bf16* __restrict__ Ahi, const bf16* __restrict__ Alo,
           const bf16* __restrict__ Bhi, const bf16* __restrict__ Blo,
           const float* __restrict__ bias, const float* __restrict__ res,
           float* __restrict__ Cf, bf16* __restrict__ Chi, bf16* __restrict__ Clo,
           int N, int K) {
    extern __shared__ __align__(128) char smraw[];
    uint32_t sb = smem_u32(smraw);

    int tid = threadIdx.x, wid = tid >> 5, lane = tid & 31;
    int wm = wid >> 1, wn = wid & 1;
    int m0 = blockIdx.y * 128, n0 = blockIdx.x * 64;

    float acc[2][4][4];
    #pragma unroll
    for (int i = 0; i < 2; i++)
        #pragma unroll
        for (int j = 0; j < 4; j++)
            #pragma unroll
            for (int r = 0; r < 4; r++) acc[i][j][r] = 0.0f;

    const int nk = K >> 6;

    auto load_stage = [&](int buf, int kt2) {
        int k0 = kt2 << 6;
        uint32_t sb0 = sb + buf * STAGE_B;
        #pragma unroll
        for (int t = 0; t < 4; t++) {
            int idx = tid + t * 256;
            int row = idx >> 3, u = idx & 7;
            uint32_t so = sb0 + (row << 7) + ((u ^ (row & 7)) << 4);
            size_t ea = (size_t)(m0 + row) * K + k0 + u * 8;
            CP16(so,         Ahi + ea);
            CP16(so + 16384, Alo + ea);
        }
        #pragma unroll
        for (int t = 0; t < 2; t++) {
            int idx = tid + t * 256;
            int row = idx >> 3, u = idx & 7;
            uint32_t so = sb0 + 32768 + (row << 7) + ((u ^ (row & 7)) << 4);
            size_t eb = (size_t)(n0 + row) * K + k0 + u * 8;
            CP16(so,        Bhi + eb);
            CP16(so + 8192, Blo + eb);
        }
    };

    load_stage(0, 0); CP_COMMIT();

    int lr = lane & 15, lu = lane >> 4;
    int bnn = wn * 32 + ((lane >> 4) << 3) + (lane & 7);
    int bus = (lane >> 3) & 1;

    for (int kt = 0; kt < nk; kt++) {
        CP_WAIT0();                       // stage kt (only pending group) ready
        __syncthreads();
        if (kt + 1 < nk) { load_stage((kt + 1) & 1, kt + 1); CP_COMMIT(); }

        uint32_t base = sb + (kt & 1) * STAGE_B;
        #pragma unroll
        for (int kk = 0; kk < 4; kk++) {
            uint32_t aH[2][4], aL[2][4], bH[2][4], bL[2][4];
            #pragma unroll
            for (int mf = 0; mf < 2; mf++) {
                int r = wm * 32 + mf * 16 + lr;
                int u = kk * 2 + lu;
                uint32_t ad = base + (r << 7) + ((u ^ (r & 7)) << 4);
                ldsm4(aH[mf], ad);
                ldsm4(aL[mf], ad + 16384);
            }
            #pragma unroll
            for (int j = 0; j < 2; j++) {
                int n = bnn + j * 16;
                int u = kk * 2 + bus;
                uint32_t bd = base + 32768 + (n << 7) + ((u ^ (n & 7)) << 4);
                ldsm4(bH[j], bd);
                ldsm4(bL[j], bd + 8192);
            }
            MMA_BLOCK_TERMMAJOR();
        }
        __syncthreads();                 // compute done before next overwrite
    }

    int r0b = m0 + wm * 32 + (lane >> 2);
    int cb  = n0 + wn * 32 + 2 * (lane & 3);
    #pragma unroll
    for (int mf = 0; mf < 2; mf++)
        #pragma unroll
        for (int nf = 0; nf < 4; nf++) {
            int c = cb + nf * 8;
            #pragma unroll
            for (int half = 0; half < 2; half++) {
                int r = r0b + mf * 16 + half * 8;
                size_t off = (size_t)r * N + c;
                epi_write<MODE>(acc[mf][nf][half * 2], acc[mf][nf][half * 2 + 1],
                                off, c, bias, res, Cf, Chi, Clo);
            }
        }
}

// ---------------- fused attention: one block per (b, h) ----------------
__global__ void __launch_bounds__(256)
attn_kernel(const float* __restrict__ qkv, const int* __restrict__ amask,
            bf16* __restrict__ ohi, bf16* __restrict__ olo) {
    __shared__ float sK[S_][DH_ + 1];
    __shared__ float sV[S_][DH_ + 1];
    __shared__ float sQ[8][DH_];
    __shared__ float sP[8][S_ + 3];
    __shared__ int   sM[S_];
    int h = blockIdx.x, b = blockIdx.y;
    int tid = threadIdx.x, lane = tid & 31, w = tid >> 5;

    for (int i = tid; i < S_ * DH_; i += 256) {
        int s = i >> 6, d = i & 63;
        size_t base = ((size_t)(b * S_ + s)) * QKVN + h * DH_ + d;
        sK[s][d] = qkv[base + D_];
        sV[s][d] = qkv[base + 2 * D_];
    }
    for (int i = tid; i < S_; i += 256)
        sM[i] = (i < NP_) ? 1 : amask[b * T_ + i - NP_];
    __syncthreads();

    for (int qi = w; qi < S_; qi += 8) {
        size_t qoff = ((size_t)(b * S_ + qi)) * QKVN + h * DH_;
        sQ[w][lane]      = qkv[qoff + lane];
        sQ[w][lane + 32] = qkv[qoff + lane + 32];
        __syncwarp();
        int nj = qi + 1;
        float sc[3];
        #pragma unroll
        for (int t = 0; t < 3; t++) {
            int j = lane + 32 * t;
            float dsum = -3.0e38f;
            if (j < nj) {
                dsum = 0.0f;
                #pragma unroll
                for (int dd = 0; dd < DH_; dd++) dsum += sQ[w][dd] * sK[j][dd];
                if (sM[j] == 0) dsum = -1.0e30f;
            }
            sc[t] = dsum;
        }
        float m = fmaxf(sc[0], fmaxf(sc[1], sc[2]));
        #pragma unroll
        for (int o2 = 16; o2 > 0; o2 >>= 1) m = fmaxf(m, __shfl_xor_sync(0xffffffffu, m, o2));
        float e[3], esum = 0.0f;
        #pragma unroll
        for (int t = 0; t < 3; t++) {
            int j = lane + 32 * t;
            e[t] = (j < nj) ? __expf(sc[t] - m) : 0.0f;
            esum += e[t];
        }
        #pragma unroll
        for (int o2 = 16; o2 > 0; o2 >>= 1) esum += __shfl_xor_sync(0xffffffffu, esum, o2);
        float inv = 1.0f / esum;
        #pragma unroll
        for (int t = 0; t < 3; t++) {
            int j = lane + 32 * t;
            if (j < nj) sP[w][j] = e[t] * inv;
        }
        __syncwarp();
        float a0 = 0.0f, a1 = 0.0f;
        for (int j = 0; j < nj; j++) {
            float p = sP[w][j];
            a0 += p * sV[j][lane];
            a1 += p * sV[j][lane + 32];
        }
        size_t ooff = ((size_t)(b * S_ + qi)) * D_ + h * DH_;
        bf16 h0 = __float2bfloat16(a0);
        ohi[ooff + lane] = h0;
        olo[ooff + lane] = __float2bfloat16(a0 - __bfloat162float(h0));
        bf16 h1 = __float2bfloat16(a1);
        ohi[ooff + lane + 32] = h1;
        olo[ooff + lane + 32] = __float2bfloat16(a1 - __bfloat162float(h1));
        __syncwarp();
    }
}

// ---------------- final: argmax gather + layernorm -> out ----------------
__global__ void __launch_bounds__(128)
final_kernel(const float* __restrict__ x, const int* __restrict__ tok,
             const float* __restrict__ g, const float* __restrict__ bb,
             float* __restrict__ out) {
    int b = blockIdx.x, tid = threadIdx.x;
    __shared__ int sval[128];
    __shared__ int srow;
    sval[tid] = (tid < T_) ? tok[b * T_ + tid] : (-2147483647 - 1);
    __syncthreads();
    if (tid == 0) {
        int best = sval[0], bi = 0;
        for (int t = 1; t < T_; t++)
            if (sval[t] > best) { best = sval[t]; bi = t; }
        srow = bi + NP_;
    }
    __syncthreads();
    int row = b * S_ + srow;
    float4 vv = ((const float4*)(x + (size_t)row * D_))[tid];
    float s  = vv.x + vv.y + vv.z + vv.w;
    float ss = vv.x * vv.x + vv.y * vv.y + vv.z * vv.z + vv.w * vv.w;
    float2 tot = block_sum2(s, ss);
    float mean = tot.x * (1.0f / D_);
    float var  = tot.y * (1.0f / D_) - mean * mean;
    float rstd = rsqrtf(var + 1e-5f);
    float4 gv = ((const float4*)g)[tid];
    float4 bv = ((const float4*)bb)[tid];
    float4 ov;
    ov.x = (vv.x - mean) * rstd * gv.x + bv.x;
    ov.y = (vv.y - mean) * rstd * gv.y + bv.y;
    ov.z = (vv.z - mean) * rstd * gv.z + bv.z;
    ov.w = (vv.w - mean) * rstd * gv.w + bv.w;
    ((float4*)(out + (size_t)b * D_))[tid] = ov;
}

// ---------------- launch ----------------
extern "C" void kernel_launch(void* const* d_in, const int* in_sizes, int n_in,
                              void* d_out, int out_size) {
    (void)in_sizes; (void)n_in; (void)out_size;
    const int*   tok   = (const int*)  d_in[0];
    const int*   amask = (const int*)  d_in[1];
    const float* gp    = (const float*)d_in[2];
    const float* sp    = (const float*)d_in[3];
    const float* temb  = (const float*)d_in[4];
    const float* pemb  = (const float*)d_in[5];
    const float* ln1g  = (const float*)d_in[6];
    const float* ln1b  = (const float*)d_in[7];
    const float* Wq    = (const float*)d_in[8];
    const float* bq    = (const float*)d_in[9];
    const float* Wk    = (const float*)d_in[10];
    const float* bk    = (const float*)d_in[11];
    const float* Wv    = (const float*)d_in[12];
    const float* bv    = (const float*)d_in[13];
    const float* Wo    = (const float*)d_in[14];
    const float* bo    = (const float*)d_in[15];
    const float* ln2g  = (const float*)d_in[16];
    const float* ln2b  = (const float*)d_in[17];
    const float* W1    = (const float*)d_in[18];
    const float* b1    = (const float*)d_in[19];
    const float* W2    = (const float*)d_in[20];
    const float* b2    = (const float*)d_in[21];
    const float* lnfg  = (const float*)d_in[22];
    const float* lnfb  = (const float*)d_in[23];
    float* out = (float*)d_out;

    float *x, *qkv, *bqkv;
    bf16 *hhi, *hlo, *ohi, *olo, *fhi, *flo;
    bf16 *wqh, *wql, *woh, *wol, *w1h, *w1l, *w2h, *w2l;
    cudaGetSymbolAddress((void**)&x,   g_x);
    cudaGetSymbolAddress((void**)&hhi, g_hhi);
    cudaGetSymbolAddress((void**)&hlo, g_hlo);
    cudaGetSymbolAddress((void**)&qkv, g_qkv);
    cudaGetSymbolAddress((void**)&ohi, g_ohi);
    cudaGetSymbolAddress((void**)&olo, g_olo);
    cudaGetSymbolAddress((void**)&fhi, g_fhi);
    cudaGetSymbolAddress((void**)&flo, g_flo);
    cudaGetSymbolAddress((void**)&wqh, w_qkv_hi);
    cudaGetSymbolAddress((void**)&wql, w_qkv_lo);
    cudaGetSymbolAddress((void**)&woh, w_o_hi);
    cudaGetSymbolAddress((void**)&wol, w_o_lo);
    cudaGetSymbolAddress((void**)&w1h, w_1_hi);
    cudaGetSymbolAddress((void**)&w1l, w_1_lo);
    cudaGetSymbolAddress((void**)&w2h, w_2_hi);
    cudaGetSymbolAddress((void**)&w2l, w_2_lo);
    cudaGetSymbolAddress((void**)&bqkv, g_bqkv);

    cudaFuncSetAttribute(gemm_mma128<0>, cudaFuncAttributeMaxDynamicSharedMemorySize, SMEM_A_TOT);
    cudaFuncSetAttribute(gemm_mma128<2>, cudaFuncAttributeMaxDynamicSharedMemorySize, SMEM_A_TOT);
    cudaFuncSetAttribute(gemm_mma64<1>,  cudaFuncAttributeMaxDynamicSharedMemorySize, SMEM_B_TOT);

    prep_kernel<<<dim3(1024, 7, NL_), 256>>>(Wq, Wk, Wv, Wo, W1, W2, bq, bk, bv,
                                             wqh, wql, woh, wol, w1h, w1l, w2h, w2l, bqkv);
    embed_kernel<<<(B_ * S_ * D_) / 256, 256>>>(tok, gp, temb, pemb, x);

    dim3 gQKV(QKVN / 128, MROWS / 128);   // (12, 77)
    dim3 gFF (FF_  / 128, MROWS / 128);   // (16, 77)
    dim3 gD64(D_   / 64,  MROWS / 128);   // (8, 77) = 616 CTAs

    for (int i = 0; i < NL_; i++) {
        if (i > 0) {
            const float* p; int bs;
            if (i < DG_) { p = gp + (size_t)i * NP_ * D_;                 bs = DG_ * NP_ * D_; }
            else         { p = sp + (size_t)(i - (NL_ - DS_)) * NP_ * D_; bs = DS_ * NP_ * D_; }
            prompt_kernel<<<(B_ * NP_ * D_) / 256, 256>>>(p, bs, x);
        }
        ln_split_kernel<<<MROWS, 128>>>(x, ln1g + i * D_, ln1b + i * D_, hhi, hlo);
        gemm_mma128<0><<<gQKV, 512, SMEM_A_TOT>>>(hhi, hlo,
            wqh + (size_t)i * QKVN * D_, wql + (size_t)i * QKVN * D_,
            bqkv + i * QKVN, nullptr, qkv, nullptr, nullptr, QKVN, D_);
        attn_kernel<<<dim3(H_, B_), 256>>>(qkv, amask, ohi, olo);
        gemm_mma64<1><<<gD64, 256, SMEM_B_TOT>>>(ohi, olo,
            woh + (size_t)i * D_ * D_, wol + (size_t)i * D_ * D_,
            bo + i * D_, x, x, nullptr, nullptr, D_, D_);
        ln_split_kernel<<<MROWS, 128>>>(x, ln2g + i * D_, ln2b + i * D_, hhi, hlo);
        gemm_mma128<2><<<gFF, 512, SMEM_A_TOT>>>(hhi, hlo,
            w1h + (size_t)i * FF_ * D_, w1l + (size_t)i * FF_ * D_,
            b1 + i * FF_, nullptr, nullptr, fhi, flo, FF_, D_);
        gemm_mma64<1><<<gD64, 256, SMEM_B_TOT>>>(fhi, flo,
            w2h + (size_t)i * D_ * FF_, w2l + (size_t)i * D_ * FF_,
            b2 + i * D_, x, x, nullptr, nullptr, D_, FF_);
    }
    final_kernel<<<B_, 128>>>(x, tok, lnfg, lnfb, out);
}